// round 11
// baseline (speedup 1.0000x reference)
#include <cuda_runtime.h>
#include <math.h>
#include <stdint.h>

#define L_SEQ  4096
#define DMODEL 1024
#define NHEADS 16
#define HDIM   64
#define LOG2E  1.4426950408889634f

// Scratch (allocation-free rule: __device__ globals)
// Storage layouts (mma k-dim is permutation-invariant when both operands agree):
// pos16: within each 16-element k-group, element (o=bit3, l=bits2:0) is stored
// at 4*(l>>1) + 2*o + (l&1). This packs the fragments of TWO consecutive
// 8-groups for quad-lane q into one contiguous 16B chunk -> LDS.128 feeds two
// mma k-steps. Applied to the d-dim of g_q/g_k and the seq-dim of g_v.
// Slot convention within an 8-group (as R10): slot q <-> elem 2q, slot q+4 <->
// elem 2q+1, under which the QK C-frag IS the PV A-frag (no shuffles).
__device__ float g_q[NHEADS * L_SEQ * HDIM];   // [h][seq][dperm], *0.125*log2e, tf32
__device__ float g_k[NHEADS * L_SEQ * HDIM];   // [h][seq][dperm], tf32
__device__ float g_v[NHEADS * HDIM * L_SEQ];   // [h][d][seqperm], tf32
__device__ float g_attn[L_SEQ * DMODEL];       // [seq][dmodel], tf32
__device__ float g_wt[4 * DMODEL * DMODEL];    // transposed tf32 weights [N][K]
__device__ float g_xr[L_SEQ * DMODEL];         // tf32-rounded x

__device__ __forceinline__ uint32_t smem_u32(const void* p) {
    uint32_t a;
    asm("{ .reg .u64 t; cvta.to.shared.u64 t, %1; cvt.u32.u64 %0, t; }" : "=r"(a) : "l"(p));
    return a;
}
__device__ __forceinline__ float to_tf32(float x) {
    uint32_t r; asm("cvt.rna.tf32.f32 %0, %1;" : "=r"(r) : "f"(x));
    return __uint_as_float(r);
}
__device__ __forceinline__ float ex2(float x) {
    float y; asm("ex2.approx.f32 %0, %1;" : "=f"(y) : "f"(x)); return y;
}
// within-16-group ks-pair interleave position
__device__ __forceinline__ int pos16(int d) {
    int l = d & 7, o = (d >> 3) & 1;
    return (d & ~15) | (((l >> 1) << 2) | (o << 1) | (l & 1));
}
__device__ __forceinline__ void mma8(float* c, uint32_t a0, uint32_t a1, uint32_t a2,
                                     uint32_t a3, uint32_t b0, uint32_t b1) {
    asm volatile(
        "mma.sync.aligned.m16n8k8.row.col.f32.tf32.tf32.f32 "
        "{%0,%1,%2,%3}, {%4,%5,%6,%7}, {%8,%9}, {%0,%1,%2,%3};"
        : "+f"(c[0]), "+f"(c[1]), "+f"(c[2]), "+f"(c[3])
        : "r"(a0), "r"(a1), "r"(a2), "r"(a3), "r"(b0), "r"(b1));
}
__device__ __forceinline__ void mma8f(float* c, float a0, float a1, float a2,
                                      float a3, float b0, float b1) {
    mma8(c, __float_as_uint(a0), __float_as_uint(a1), __float_as_uint(a2),
         __float_as_uint(a3), __float_as_uint(b0), __float_as_uint(b1));
}

// ---------------------------------------------------------------------------
__global__ __launch_bounds__(256) void round_x(const float* __restrict__ x,
                                               float* __restrict__ xr) {
    int i = (blockIdx.x * 256 + threadIdx.x) * 4;
    float4 v = *(const float4*)&x[i];
    *(float4*)&xr[i] = make_float4(to_tf32(v.x), to_tf32(v.y), to_tf32(v.z), to_tf32(v.w));
}

// ---------------------------------------------------------------------------
__global__ __launch_bounds__(256) void transpose_w(const float* __restrict__ w0,
                                                   const float* __restrict__ w1,
                                                   const float* __restrict__ w2,
                                                   const float* __restrict__ w3,
                                                   float* __restrict__ dst) {
    __shared__ float tile[32][33];
    const int z = blockIdx.z;
    const float* src = (z == 0) ? w0 : (z == 1) ? w1 : (z == 2) ? w2 : w3;
    float* d = dst + (size_t)z * DMODEL * DMODEL;
    const int tx = threadIdx.x, ty = threadIdx.y;
    const int x = blockIdx.x * 32 + tx;
    const int y0 = blockIdx.y * 32;
#pragma unroll
    for (int j = ty; j < 32; j += 8)
        tile[j][tx] = to_tf32(src[(size_t)(y0 + j) * DMODEL + x]);
    __syncthreads();
    const int xo = blockIdx.y * 32 + tx;
    const int yo0 = blockIdx.x * 32;
#pragma unroll
    for (int j = ty; j < 32; j += 8)
        d[(size_t)(yo0 + j) * DMODEL + xo] = tile[tx][j];
}

// ---------------------------------------------------------------------------
// tf32 mma.sync GEMM: CTA 128x128x32, 8 warps, 3-stage cp.async pipeline.
// FUSED: z=0 -> g_q (scaled, d pos16-permuted), z=1 -> g_k (d pos16-permuted),
//        z=2 -> g_v (transposed, seq pos16-permuted). All tf32-rounded.
// !FUSED: plain C[row*N+col].
// ---------------------------------------------------------------------------
#define GBK 32
#define STG_FLOATS (128 * 36)
#define SMEM_GEMM3 (3 * 2 * STG_FLOATS * 4)

template <bool FUSED>
__global__ __launch_bounds__(256, 2)
void gemm_mma(const float* __restrict__ A, const float* __restrict__ WtBase,
              float* __restrict__ C0, float* __restrict__ C1, float* __restrict__ C2,
              int M, int N, int K, float qscale) {
    extern __shared__ float smf[];
    const uint32_t sbase = smem_u32(smf);
    const int tid = threadIdx.x;
    const int wid = tid >> 5;
    const int lane = tid & 31;
    const int row0 = blockIdx.y * 128;
    const int col0 = blockIdx.x * 128;
    const int z = FUSED ? (int)blockIdx.z : 0;
    const float* Bt = WtBase + (size_t)z * DMODEL * DMODEL;
    const int wm = (wid & 1) * 64;
    const int wn = (wid >> 1) * 32;
    const int g = lane >> 2;
    const int q = lane & 3;

    const int l_row = tid >> 3;
    const int l_c   = tid & 7;

    float c[4][4][4];
#pragma unroll
    for (int mt = 0; mt < 4; mt++)
#pragma unroll
        for (int nt = 0; nt < 4; nt++)
#pragma unroll
            for (int r = 0; r < 4; r++) c[mt][nt][r] = 0.f;

    auto stage_load = [&](int kb, int s) {
        const int k0 = kb * GBK;
#pragma unroll
        for (int i = 0; i < 4; i++) {
            int r = l_row + i * 32;
            uint32_t da = sbase + (uint32_t)(s * 2 * STG_FLOATS + r * 36 + l_c * 4) * 4u;
            const float* ga = &A[(size_t)(row0 + r) * K + k0 + l_c * 4];
            asm volatile("cp.async.cg.shared.global [%0], [%1], 16;" :: "r"(da), "l"(ga));
            uint32_t db = da + (uint32_t)STG_FLOATS * 4u;
            const float* gb = &Bt[(size_t)(col0 + r) * K + k0 + l_c * 4];
            asm volatile("cp.async.cg.shared.global [%0], [%1], 16;" :: "r"(db), "l"(gb));
        }
        asm volatile("cp.async.commit_group;");
    };

    const int NK = K / GBK;
    stage_load(0, 0);
    stage_load(1, 1);

    int s = 0;
    for (int kb = 0; kb < NK; kb++) {
        if (kb + 1 < NK) {
            asm volatile("cp.async.wait_group 1;");
        } else {
            asm volatile("cp.async.wait_group 0;");
        }
        __syncthreads();
        if (kb + 2 < NK) stage_load(kb + 2, (kb + 2) % 3);

        const float* As = smf + s * 2 * STG_FLOATS;
        const float* Bs = As + STG_FLOATS;
        const float* pa = &As[(wm + g) * 36 + q];
        const float* pb = &Bs[(wn + g) * 36 + q];

#pragma unroll
        for (int ks = 0; ks < 4; ks++) {
            uint32_t af[4][4], bf[4][2];
#pragma unroll
            for (int mt = 0; mt < 4; mt++) {
                af[mt][0] = __float_as_uint(pa[(mt * 16 + 0) * 36 + ks * 8 + 0]);
                af[mt][1] = __float_as_uint(pa[(mt * 16 + 8) * 36 + ks * 8 + 0]);
                af[mt][2] = __float_as_uint(pa[(mt * 16 + 0) * 36 + ks * 8 + 4]);
                af[mt][3] = __float_as_uint(pa[(mt * 16 + 8) * 36 + ks * 8 + 4]);
            }
#pragma unroll
            for (int nt = 0; nt < 4; nt++) {
                bf[nt][0] = __float_as_uint(pb[(nt * 8) * 36 + ks * 8 + 0]);
                bf[nt][1] = __float_as_uint(pb[(nt * 8) * 36 + ks * 8 + 4]);
            }
#pragma unroll
            for (int mt = 0; mt < 4; mt++)
#pragma unroll
                for (int nt = 0; nt < 4; nt++)
                    mma8(c[mt][nt], af[mt][0], af[mt][1], af[mt][2], af[mt][3],
                         bf[nt][0], bf[nt][1]);
        }
        s = (s + 1) % 3;
    }

    const float scale = (FUSED && z == 0) ? qscale : 1.0f;
#pragma unroll
    for (int mt = 0; mt < 4; mt++) {
#pragma unroll
        for (int hr = 0; hr < 2; hr++) {
            int row = row0 + wm + mt * 16 + g + hr * 8;
#pragma unroll
            for (int nt = 0; nt < 4; nt++) {
                int col = col0 + wn + nt * 8 + q * 2;
                float vx = c[mt][nt][hr * 2] * scale;
                float vy = c[mt][nt][hr * 2 + 1] * scale;
                if (!FUSED) {
                    *(float2*)&C0[(size_t)row * N + col] = make_float2(vx, vy);
                } else {
                    vx = to_tf32(vx); vy = to_tf32(vy);
                    int head = col >> 6, d0 = col & 63;
                    if (z == 2) {
                        // seq pos16-permuted transposed store
                        int sp = pos16(row & 127) + (row & ~127);
                        // (row&127 keeps pos16's group math valid; groups of 16)
                        sp = (row & ~15) | (pos16(row & 15) & 15);
                        C2[((size_t)(head * 64 + d0)) * M + sp] = vx;
                        C2[((size_t)(head * 64 + d0 + 1)) * M + sp] = vy;
                    } else {
                        float* C = (z == 0) ? C0 : C1;
                        size_t base = ((size_t)head * M + row) * 64;
                        // d0 even -> pos16(d0), pos16(d0+1) contiguous
                        *(float2*)&C[base + pos16(d0)] = make_float2(vx, vy);
                    }
                }
            }
        }
    }
}

// ---------------------------------------------------------------------------
// Tensor-core flash attention, diagonal-first tiles, LDS.128 ks-pair fragment
// loads (XOR-swizzled, conflict-free), shuffle-free P reuse, l-sum via a 9th
// "ones" V column on the tensor core.
// Block = (head, 128 q-rows), 8 warps x 16 rows. 64-key double-buffered tiles.
// Smem floats: Q 128*64, K 2*64*64, V 2*72*64 (rows 64-71 = ones).
// ---------------------------------------------------------------------------
#define AT_QOFF   0
#define AT_KOFF   8192
#define AT_KSTRIDE 4096
#define AT_VOFF   16384
#define AT_VSTRIDE 4608
#define AT_FLOATS 25600   // 102400 B

__global__ __launch_bounds__(256, 2) void attn_mma() {
    extern __shared__ float sm[];
    const uint32_t sb = smem_u32(sm);
    const int h  = blockIdx.y;
    const int bx = (int)gridDim.x - 1 - (int)blockIdx.x;  // big tiles first
    const int i0 = bx * 128;
    const int tid = threadIdx.x;
    const int w = tid >> 5;
    const int lane = tid & 31;
    const int g = lane >> 2, q = lane & 3;
    const int qr = w * 16;
    const int swz = (g & 1) << 2;          // XOR chunk swizzle for this thread's rows
    const float slope2 = ex2(-0.5f * (float)(h + 1)) * LOG2E;

    const float* Qs = sm + AT_QOFF;

    auto load_tile = [&](int t, int s) {
        const int j0 = t * 64;
        const float* kp = g_k + ((size_t)h * L_SEQ + j0) * HDIM;
        const float* vp = g_v + (size_t)h * HDIM * L_SEQ + j0;
        const uint32_t kd = sb + (AT_KOFF + s * AT_KSTRIDE) * 4u;
        const uint32_t vd = sb + (AT_VOFF + s * AT_VSTRIDE) * 4u;
#pragma unroll
        for (int i = 0; i < 4; i++) {
            int cc = tid + i * 256;
            int row = cc >> 4, c16 = cc & 15;
            int dc = c16 ^ ((row & 1) << 2);
            asm volatile("cp.async.cg.shared.global [%0], [%1], 16;"
                         :: "r"(kd + (uint32_t)(row * 64 + dc * 4) * 4u),
                            "l"(kp + (size_t)row * HDIM + c16 * 4));
            asm volatile("cp.async.cg.shared.global [%0], [%1], 16;"
                         :: "r"(vd + (uint32_t)(row * 64 + dc * 4) * 4u),
                            "l"(vp + (size_t)row * L_SEQ + c16 * 4));
        }
        asm volatile("cp.async.commit_group;");
    };

    const int ntiles = 2 * bx + 2;
    const int tstart = ntiles - 1;

    // ones rows (64-71) of both V buffers
#pragma unroll
    for (int i = tid; i < 512; i += 256) {
        sm[AT_VOFF + 4096 + i] = 1.0f;
        sm[AT_VOFF + AT_VSTRIDE + 4096 + i] = 1.0f;
    }
    {
        const float* qp = g_q + ((size_t)h * L_SEQ + i0) * HDIM;
        const uint32_t qd = sb + AT_QOFF * 4u;
#pragma unroll
        for (int i = 0; i < 8; i++) {
            int cc = tid + i * 256;
            int row = cc >> 4, c16 = cc & 15;
            int dc = c16 ^ ((row & 1) << 2);
            asm volatile("cp.async.cg.shared.global [%0], [%1], 16;"
                         :: "r"(qd + (uint32_t)(row * 64 + dc * 4) * 4u),
                            "l"(qp + (size_t)row * HDIM + c16 * 4));
        }
        load_tile(tstart, tstart & 1);
    }

    float mA = -INFINITY, mB = -INFINITY;
    float O[9][4];   // O[8] = ones column -> row sums (lA in c0, lB in c2)
#pragma unroll
    for (int nt = 0; nt < 9; nt++)
#pragma unroll
        for (int r = 0; r < 4; r++) O[nt][r] = 0.f;

    const int iA = i0 + qr + g;
    const int iB = iA + 8;

    for (int t = tstart; t >= 0; t--) {
        if (t > 0) {
            load_tile(t - 1, (t - 1) & 1);
            asm volatile("cp.async.wait_group 1;");
        } else {
            asm volatile("cp.async.wait_group 0;");
        }
        __syncthreads();

        const int j0 = t * 64;
        if (j0 <= i0 + qr + 15) {
            const float* Ks = sm + AT_KOFF + (t & 1) * AT_KSTRIDE;
            const float* Vs = sm + AT_VOFF + (t & 1) * AT_VSTRIDE;

            // ---- S = Q K^T : LDS.128 ks-pair fragments ----
            float s[8][4];
#pragma unroll
            for (int nt = 0; nt < 8; nt++)
#pragma unroll
                for (int r = 0; r < 4; r++) s[nt][r] = 0.f;

#pragma unroll
            for (int kp = 0; kp < 4; kp++) {
                const int co = ((kp * 4 + q) ^ swz) * 4;
                float4 qa = *(const float4*)&Qs[(qr + g) * 64 + co];
                float4 qb = *(const float4*)&Qs[(qr + g + 8) * 64 + co];
#pragma unroll
                for (int nt = 0; nt < 8; nt++) {
                    float4 kf = *(const float4*)&Ks[(nt * 8 + g) * 64 + co];
                    mma8f(s[nt], qa.x, qb.x, qa.y, qb.y, kf.x, kf.y);
                    mma8f(s[nt], qa.z, qb.z, qa.w, qb.w, kf.z, kf.w);
                }
            }

            // ---- ALiBi + causal ----
            const bool needmask = (j0 + 63 > i0 + qr);
#pragma unroll
            for (int nt = 0; nt < 8; nt++) {
                int j = j0 + nt * 8 + 2 * q;
                s[nt][0] -= slope2 * (float)(iA - j);
                s[nt][1] -= slope2 * (float)(iA - j - 1);
                s[nt][2] -= slope2 * (float)(iB - j);
                s[nt][3] -= slope2 * (float)(iB - j - 1);
                if (needmask) {
                    if (j > iA)     s[nt][0] = -INFINITY;
                    if (j + 1 > iA) s[nt][1] = -INFINITY;
                    if (j > iB)     s[nt][2] = -INFINITY;
                    if (j + 1 > iB) s[nt][3] = -INFINITY;
                }
            }

            // ---- online softmax (diagonal-first: rescale rarely fires) ----
            float mxA = -INFINITY, mxB = -INFINITY;
#pragma unroll
            for (int nt = 0; nt < 8; nt++) {
                mxA = fmaxf(mxA, fmaxf(s[nt][0], s[nt][1]));
                mxB = fmaxf(mxB, fmaxf(s[nt][2], s[nt][3]));
            }
            mxA = fmaxf(mxA, __shfl_xor_sync(0xffffffffu, mxA, 1));
            mxA = fmaxf(mxA, __shfl_xor_sync(0xffffffffu, mxA, 2));
            mxB = fmaxf(mxB, __shfl_xor_sync(0xffffffffu, mxB, 1));
            mxB = fmaxf(mxB, __shfl_xor_sync(0xffffffffu, mxB, 2));
            const float mAn = fmaxf(mA, mxA), mBn = fmaxf(mB, mxB);
            bool changed = (mAn != mA) || (mBn != mB);
            if (__any_sync(0xffffffffu, changed)) {
                const float cA = ex2(mA - mAn), cB = ex2(mB - mBn);
                mA = mAn; mB = mBn;
#pragma unroll
                for (int nt = 0; nt < 9; nt++) {
                    O[nt][0] *= cA; O[nt][1] *= cA;
                    O[nt][2] *= cB; O[nt][3] *= cB;
                }
            }
#pragma unroll
            for (int nt = 0; nt < 8; nt++) {
                s[nt][0] = to_tf32(ex2(s[nt][0] - mA));
                s[nt][1] = to_tf32(ex2(s[nt][1] - mA));
                s[nt][2] = to_tf32(ex2(s[nt][2] - mB));
                s[nt][3] = to_tf32(ex2(s[nt][3] - mB));
            }

            // ---- O += P V (incl. ones column -> l) ----
#pragma unroll
            for (int kp = 0; kp < 4; kp++) {
                const int co = ((kp * 4 + q) ^ swz) * 4;
#pragma unroll
                for (int nt = 0; nt < 9; nt++) {
                    float4 vf = *(const float4*)&Vs[(nt * 8 + g) * 64 + co];
                    mma8f(O[nt], s[2 * kp][0], s[2 * kp][2], s[2 * kp][1],
                          s[2 * kp][3], vf.x, vf.y);
                    mma8f(O[nt], s[2 * kp + 1][0], s[2 * kp + 1][2], s[2 * kp + 1][1],
                          s[2 * kp + 1][3], vf.z, vf.w);
                }
            }
        }
        __syncthreads();
    }

    const float invA = 1.0f / O[8][0], invB = 1.0f / O[8][2];
#pragma unroll
    for (int nt = 0; nt < 8; nt++) {
        int col = h * HDIM + nt * 8 + 2 * q;
        *(float2*)&g_attn[(size_t)iA * DMODEL + col] =
            make_float2(to_tf32(O[nt][0] * invA), to_tf32(O[nt][1] * invA));
        *(float2*)&g_attn[(size_t)iB * DMODEL + col] =
            make_float2(to_tf32(O[nt][2] * invB), to_tf32(O[nt][3] * invB));
    }
}

// ---------------------------------------------------------------------------
extern "C" void kernel_launch(void* const* d_in, const int* in_sizes, int n_in,
                              void* d_out, int out_size) {
    const float* x  = (const float*)d_in[0];
    const float* qw = (const float*)d_in[1];
    const float* kw = (const float*)d_in[2];
    const float* vw = (const float*)d_in[3];
    const float* ow = (const float*)d_in[4];
    float* out = (float*)d_out;

    float *pq, *pk, *pv, *pa, *pwt, *pxr;
    cudaGetSymbolAddress((void**)&pq, g_q);
    cudaGetSymbolAddress((void**)&pk, g_k);
    cudaGetSymbolAddress((void**)&pv, g_v);
    cudaGetSymbolAddress((void**)&pa, g_attn);
    cudaGetSymbolAddress((void**)&pwt, g_wt);
    cudaGetSymbolAddress((void**)&pxr, g_xr);

    const int SMEM_ATTN = AT_FLOATS * 4;  // 102400 B
    cudaFuncSetAttribute(gemm_mma<true>,  cudaFuncAttributeMaxDynamicSharedMemorySize, SMEM_GEMM3);
    cudaFuncSetAttribute(gemm_mma<false>, cudaFuncAttributeMaxDynamicSharedMemorySize, SMEM_GEMM3);
    cudaFuncSetAttribute(attn_mma, cudaFuncAttributeMaxDynamicSharedMemorySize, SMEM_ATTN);

    round_x<<<(L_SEQ * DMODEL) / (256 * 4), 256>>>(x, pxr);
    dim3 tb(32, 8);
    dim3 tg(DMODEL / 32, DMODEL / 32, 4);
    transpose_w<<<tg, tb>>>(qw, kw, vw, ow, pwt);

    const float qscale = 0.125f * LOG2E;
    dim3 gqkv(DMODEL / 128, L_SEQ / 128, 3);
    gemm_mma<true><<<gqkv, 256, SMEM_GEMM3>>>(pxr, pwt, pq, pk, pv,
                                              L_SEQ, DMODEL, DMODEL, qscale);

    dim3 ga(L_SEQ / 128, NHEADS);
    attn_mma<<<ga, 256, SMEM_ATTN>>>();

    dim3 gout(DMODEL / 128, L_SEQ / 128, 1);
    gemm_mma<false><<<gout, 256, SMEM_GEMM3>>>(pa, pwt + 3 * (size_t)DMODEL * DMODEL,
                                               out, nullptr, nullptr,
                                               L_SEQ, DMODEL, DMODEL, 1.0f);
}

// round 12
// speedup vs baseline: 1.0143x; 1.0143x over previous
#include <cuda_runtime.h>
#include <math.h>
#include <stdint.h>

#define L_SEQ  4096
#define DMODEL 1024
#define NHEADS 16
#define HDIM   64
#define LOG2E  1.4426950408889634f

// Scratch (allocation-free rule: __device__ globals)
// Storage layouts (mma k-dim is permutation-invariant when both operands agree):
// pos16: within each 16-element k-group, element (o=bit3, l=bits2:0) is stored
// at 4*(l>>1) + 2*o + (l&1): packs the fragments of TWO consecutive 8-groups
// for quad-lane q into one 16B chunk -> LDS.128 feeds two mma k-steps.
// Applied to d-dim of g_q/g_k and seq-dim of g_v. Slot convention within an
// 8-group: slot q <-> elem 2q, slot q+4 <-> elem 2q+1, under which the QK
// C-frag IS the PV A-frag (no shuffles).
__device__ float g_q[NHEADS * L_SEQ * HDIM];   // [h][seq][dperm], *0.125*log2e, tf32
__device__ float g_k[NHEADS * L_SEQ * HDIM];   // [h][seq][dperm], tf32
__device__ float g_v[NHEADS * HDIM * L_SEQ];   // [h][d][seqperm], tf32
__device__ float g_attn[L_SEQ * DMODEL];       // [seq][dmodel], tf32
__device__ float g_wt[4 * DMODEL * DMODEL];    // transposed tf32 weights [N][K]
__device__ float g_xr[L_SEQ * DMODEL];         // tf32-rounded x

__device__ __forceinline__ uint32_t smem_u32(const void* p) {
    uint32_t a;
    asm("{ .reg .u64 t; cvta.to.shared.u64 t, %1; cvt.u32.u64 %0, t; }" : "=r"(a) : "l"(p));
    return a;
}
__device__ __forceinline__ float to_tf32(float x) {
    uint32_t r; asm("cvt.rna.tf32.f32 %0, %1;" : "=r"(r) : "f"(x));
    return __uint_as_float(r);
}
__device__ __forceinline__ float ex2(float x) {
    float y; asm("ex2.approx.f32 %0, %1;" : "=f"(y) : "f"(x)); return y;
}
// within-16-group ks-pair interleave position
__device__ __forceinline__ int pos16(int d) {
    int l = d & 7, o = (d >> 3) & 1;
    return (d & ~15) | (((l >> 1) << 2) | (o << 1) | (l & 1));
}
__device__ __forceinline__ void mma8(float* c, uint32_t a0, uint32_t a1, uint32_t a2,
                                     uint32_t a3, uint32_t b0, uint32_t b1) {
    asm volatile(
        "mma.sync.aligned.m16n8k8.row.col.f32.tf32.tf32.f32 "
        "{%0,%1,%2,%3}, {%4,%5,%6,%7}, {%8,%9}, {%0,%1,%2,%3};"
        : "+f"(c[0]), "+f"(c[1]), "+f"(c[2]), "+f"(c[3])
        : "r"(a0), "r"(a1), "r"(a2), "r"(a3), "r"(b0), "r"(b1));
}
__device__ __forceinline__ void mma8f(float* c, float a0, float a1, float a2,
                                      float a3, float b0, float b1) {
    mma8(c, __float_as_uint(a0), __float_as_uint(a1), __float_as_uint(a2),
         __float_as_uint(a3), __float_as_uint(b0), __float_as_uint(b1));
}

// ---------------------------------------------------------------------------
__global__ __launch_bounds__(256) void round_x(const float* __restrict__ x,
                                               float* __restrict__ xr) {
    int i = (blockIdx.x * 256 + threadIdx.x) * 4;
    float4 v = *(const float4*)&x[i];
    *(float4*)&xr[i] = make_float4(to_tf32(v.x), to_tf32(v.y), to_tf32(v.z), to_tf32(v.w));
}

// ---------------------------------------------------------------------------
__global__ __launch_bounds__(256) void transpose_w(const float* __restrict__ w0,
                                                   const float* __restrict__ w1,
                                                   const float* __restrict__ w2,
                                                   const float* __restrict__ w3,
                                                   float* __restrict__ dst) {
    __shared__ float tile[32][33];
    const int z = blockIdx.z;
    const float* src = (z == 0) ? w0 : (z == 1) ? w1 : (z == 2) ? w2 : w3;
    float* d = dst + (size_t)z * DMODEL * DMODEL;
    const int tx = threadIdx.x, ty = threadIdx.y;
    const int x = blockIdx.x * 32 + tx;
    const int y0 = blockIdx.y * 32;
#pragma unroll
    for (int j = ty; j < 32; j += 8)
        tile[j][tx] = to_tf32(src[(size_t)(y0 + j) * DMODEL + x]);
    __syncthreads();
    const int xo = blockIdx.y * 32 + tx;
    const int yo0 = blockIdx.x * 32;
#pragma unroll
    for (int j = ty; j < 32; j += 8)
        d[(size_t)(yo0 + j) * DMODEL + xo] = tile[tx][j];
}

// ---------------------------------------------------------------------------
// tf32 mma.sync GEMM: CTA 128x128x32, 8 warps, 3-stage cp.async pipeline.
// FUSED: z=0 -> g_q (scaled, d pos16-permuted), z=1 -> g_k (d pos16-permuted),
//        z=2 -> g_v (transposed, seq pos16-permuted). All tf32-rounded.
// !FUSED: plain C[row*N+col].
// ---------------------------------------------------------------------------
#define GBK 32
#define STG_FLOATS (128 * 36)
#define SMEM_GEMM3 (3 * 2 * STG_FLOATS * 4)

template <bool FUSED>
__global__ __launch_bounds__(256, 2)
void gemm_mma(const float* __restrict__ A, const float* __restrict__ WtBase,
              float* __restrict__ C0, float* __restrict__ C1, float* __restrict__ C2,
              int M, int N, int K, float qscale) {
    extern __shared__ float smf[];
    const uint32_t sbase = smem_u32(smf);
    const int tid = threadIdx.x;
    const int wid = tid >> 5;
    const int lane = tid & 31;
    const int row0 = blockIdx.y * 128;
    const int col0 = blockIdx.x * 128;
    const int z = FUSED ? (int)blockIdx.z : 0;
    const float* Bt = WtBase + (size_t)z * DMODEL * DMODEL;
    const int wm = (wid & 1) * 64;
    const int wn = (wid >> 1) * 32;
    const int g = lane >> 2;
    const int q = lane & 3;

    const int l_row = tid >> 3;
    const int l_c   = tid & 7;

    float c[4][4][4];
#pragma unroll
    for (int mt = 0; mt < 4; mt++)
#pragma unroll
        for (int nt = 0; nt < 4; nt++)
#pragma unroll
            for (int r = 0; r < 4; r++) c[mt][nt][r] = 0.f;

    auto stage_load = [&](int kb, int s) {
        const int k0 = kb * GBK;
#pragma unroll
        for (int i = 0; i < 4; i++) {
            int r = l_row + i * 32;
            uint32_t da = sbase + (uint32_t)(s * 2 * STG_FLOATS + r * 36 + l_c * 4) * 4u;
            const float* ga = &A[(size_t)(row0 + r) * K + k0 + l_c * 4];
            asm volatile("cp.async.cg.shared.global [%0], [%1], 16;" :: "r"(da), "l"(ga));
            uint32_t db = da + (uint32_t)STG_FLOATS * 4u;
            const float* gb = &Bt[(size_t)(col0 + r) * K + k0 + l_c * 4];
            asm volatile("cp.async.cg.shared.global [%0], [%1], 16;" :: "r"(db), "l"(gb));
        }
        asm volatile("cp.async.commit_group;");
    };

    const int NK = K / GBK;
    stage_load(0, 0);
    stage_load(1, 1);

    int s = 0;
    for (int kb = 0; kb < NK; kb++) {
        if (kb + 1 < NK) {
            asm volatile("cp.async.wait_group 1;");
        } else {
            asm volatile("cp.async.wait_group 0;");
        }
        __syncthreads();
        if (kb + 2 < NK) stage_load(kb + 2, (kb + 2) % 3);

        const float* As = smf + s * 2 * STG_FLOATS;
        const float* Bs = As + STG_FLOATS;
        const float* pa = &As[(wm + g) * 36 + q];
        const float* pb = &Bs[(wn + g) * 36 + q];

#pragma unroll
        for (int ks = 0; ks < 4; ks++) {
            uint32_t af[4][4], bf[4][2];
#pragma unroll
            for (int mt = 0; mt < 4; mt++) {
                af[mt][0] = __float_as_uint(pa[(mt * 16 + 0) * 36 + ks * 8 + 0]);
                af[mt][1] = __float_as_uint(pa[(mt * 16 + 8) * 36 + ks * 8 + 0]);
                af[mt][2] = __float_as_uint(pa[(mt * 16 + 0) * 36 + ks * 8 + 4]);
                af[mt][3] = __float_as_uint(pa[(mt * 16 + 8) * 36 + ks * 8 + 4]);
            }
#pragma unroll
            for (int nt = 0; nt < 4; nt++) {
                bf[nt][0] = __float_as_uint(pb[(nt * 8) * 36 + ks * 8 + 0]);
                bf[nt][1] = __float_as_uint(pb[(nt * 8) * 36 + ks * 8 + 4]);
            }
#pragma unroll
            for (int mt = 0; mt < 4; mt++)
#pragma unroll
                for (int nt = 0; nt < 4; nt++)
                    mma8(c[mt][nt], af[mt][0], af[mt][1], af[mt][2], af[mt][3],
                         bf[nt][0], bf[nt][1]);
        }
        s = (s + 1) % 3;
    }

    const float scale = (FUSED && z == 0) ? qscale : 1.0f;
#pragma unroll
    for (int mt = 0; mt < 4; mt++) {
#pragma unroll
        for (int hr = 0; hr < 2; hr++) {
            int row = row0 + wm + mt * 16 + g + hr * 8;
#pragma unroll
            for (int nt = 0; nt < 4; nt++) {
                int col = col0 + wn + nt * 8 + q * 2;
                float vx = c[mt][nt][hr * 2] * scale;
                float vy = c[mt][nt][hr * 2 + 1] * scale;
                if (!FUSED) {
                    *(float2*)&C0[(size_t)row * N + col] = make_float2(vx, vy);
                } else {
                    vx = to_tf32(vx); vy = to_tf32(vy);
                    int head = col >> 6, d0 = col & 63;
                    if (z == 2) {
                        // seq pos16-permuted transposed store
                        int sp = (row & ~15) | (pos16(row & 15) & 15);
                        C2[((size_t)(head * 64 + d0)) * M + sp] = vx;
                        C2[((size_t)(head * 64 + d0 + 1)) * M + sp] = vy;
                    } else {
                        float* C = (z == 0) ? C0 : C1;
                        size_t base = ((size_t)head * M + row) * 64;
                        // d0 even -> pos16(d0), pos16(d0+1) contiguous
                        *(float2*)&C[base + pos16(d0)] = make_float2(vx, vy);
                    }
                }
            }
        }
    }
}

// ---------------------------------------------------------------------------
// Tensor-core flash attention, diagonal-first tiles, LDS.128 ks-pair fragment
// loads (XOR-swizzled, conflict-free), shuffle-free P reuse, scalar l-sums.
// Block = (head, 128 q-rows), 8 warps x 16 rows. 64-key double-buffered tiles.
// Smem floats: Q 128*64, K 2*64*64, V 2*64*64 = 24576 (98304 B).
// ---------------------------------------------------------------------------
#define AT_QOFF    0
#define AT_KOFF    8192
#define AT_KSTRIDE 4096
#define AT_VOFF    16384
#define AT_VSTRIDE 4096
#define AT_FLOATS  24576

__global__ __launch_bounds__(256, 2) void attn_mma() {
    extern __shared__ float sm[];
    const uint32_t sb = smem_u32(sm);
    const int h  = blockIdx.y;
    const int bx = (int)gridDim.x - 1 - (int)blockIdx.x;  // big tiles first
    const int i0 = bx * 128;
    const int tid = threadIdx.x;
    const int w = tid >> 5;
    const int lane = tid & 31;
    const int g = lane >> 2, q = lane & 3;
    const int qr = w * 16;
    const int swz = (g & 1) << 2;          // XOR chunk swizzle for this thread's rows
    const float slope2 = ex2(-0.5f * (float)(h + 1)) * LOG2E;

    const float* Qs = sm + AT_QOFF;

    auto load_tile = [&](int t, int s) {
        const int j0 = t * 64;
        const float* kp = g_k + ((size_t)h * L_SEQ + j0) * HDIM;
        const float* vp = g_v + (size_t)h * HDIM * L_SEQ + j0;
        const uint32_t kd = sb + (AT_KOFF + s * AT_KSTRIDE) * 4u;
        const uint32_t vd = sb + (AT_VOFF + s * AT_VSTRIDE) * 4u;
#pragma unroll
        for (int i = 0; i < 4; i++) {
            int cc = tid + i * 256;
            int row = cc >> 4, c16 = cc & 15;
            int dc = c16 ^ ((row & 1) << 2);
            asm volatile("cp.async.cg.shared.global [%0], [%1], 16;"
                         :: "r"(kd + (uint32_t)(row * 64 + dc * 4) * 4u),
                            "l"(kp + (size_t)row * HDIM + c16 * 4));
            asm volatile("cp.async.cg.shared.global [%0], [%1], 16;"
                         :: "r"(vd + (uint32_t)(row * 64 + dc * 4) * 4u),
                            "l"(vp + (size_t)row * L_SEQ + c16 * 4));
        }
        asm volatile("cp.async.commit_group;");
    };

    const int ntiles = 2 * bx + 2;
    const int tstart = ntiles - 1;

    {
        const float* qp = g_q + ((size_t)h * L_SEQ + i0) * HDIM;
        const uint32_t qd = sb + AT_QOFF * 4u;
#pragma unroll
        for (int i = 0; i < 8; i++) {
            int cc = tid + i * 256;
            int row = cc >> 4, c16 = cc & 15;
            int dc = c16 ^ ((row & 1) << 2);
            asm volatile("cp.async.cg.shared.global [%0], [%1], 16;"
                         :: "r"(qd + (uint32_t)(row * 64 + dc * 4) * 4u),
                            "l"(qp + (size_t)row * HDIM + c16 * 4));
        }
        load_tile(tstart, tstart & 1);
    }

    float mA = -INFINITY, mB = -INFINITY, lA = 0.f, lB = 0.f;
    float O[8][4];
#pragma unroll
    for (int nt = 0; nt < 8; nt++)
#pragma unroll
        for (int r = 0; r < 4; r++) O[nt][r] = 0.f;

    const int iA = i0 + qr + g;
    const int iB = iA + 8;

    for (int t = tstart; t >= 0; t--) {
        if (t > 0) {
            load_tile(t - 1, (t - 1) & 1);
            asm volatile("cp.async.wait_group 1;");
        } else {
            asm volatile("cp.async.wait_group 0;");
        }
        __syncthreads();

        const int j0 = t * 64;
        if (j0 <= i0 + qr + 15) {
            const float* Ks = sm + AT_KOFF + (t & 1) * AT_KSTRIDE;
            const float* Vs = sm + AT_VOFF + (t & 1) * AT_VSTRIDE;

            // ---- S = Q K^T : LDS.128 ks-pair fragments ----
            float s[8][4];
#pragma unroll
            for (int nt = 0; nt < 8; nt++)
#pragma unroll
                for (int r = 0; r < 4; r++) s[nt][r] = 0.f;

#pragma unroll
            for (int kp = 0; kp < 4; kp++) {
                const int co = ((kp * 4 + q) ^ swz) * 4;
                float4 qa = *(const float4*)&Qs[(qr + g) * 64 + co];
                float4 qb = *(const float4*)&Qs[(qr + g + 8) * 64 + co];
#pragma unroll
                for (int nt = 0; nt < 8; nt++) {
                    float4 kf = *(const float4*)&Ks[(nt * 8 + g) * 64 + co];
                    mma8f(s[nt], qa.x, qb.x, qa.y, qb.y, kf.x, kf.y);
                    mma8f(s[nt], qa.z, qb.z, qa.w, qb.w, kf.z, kf.w);
                }
            }

            // ---- ALiBi + causal ----
            const bool needmask = (j0 + 63 > i0 + qr);
#pragma unroll
            for (int nt = 0; nt < 8; nt++) {
                int j = j0 + nt * 8 + 2 * q;
                s[nt][0] -= slope2 * (float)(iA - j);
                s[nt][1] -= slope2 * (float)(iA - j - 1);
                s[nt][2] -= slope2 * (float)(iB - j);
                s[nt][3] -= slope2 * (float)(iB - j - 1);
                if (needmask) {
                    if (j > iA)     s[nt][0] = -INFINITY;
                    if (j + 1 > iA) s[nt][1] = -INFINITY;
                    if (j > iB)     s[nt][2] = -INFINITY;
                    if (j + 1 > iB) s[nt][3] = -INFINITY;
                }
            }

            // ---- online softmax (diagonal-first: rescale rarely fires) ----
            float mxA = -INFINITY, mxB = -INFINITY;
#pragma unroll
            for (int nt = 0; nt < 8; nt++) {
                mxA = fmaxf(mxA, fmaxf(s[nt][0], s[nt][1]));
                mxB = fmaxf(mxB, fmaxf(s[nt][2], s[nt][3]));
            }
            mxA = fmaxf(mxA, __shfl_xor_sync(0xffffffffu, mxA, 1));
            mxA = fmaxf(mxA, __shfl_xor_sync(0xffffffffu, mxA, 2));
            mxB = fmaxf(mxB, __shfl_xor_sync(0xffffffffu, mxB, 1));
            mxB = fmaxf(mxB, __shfl_xor_sync(0xffffffffu, mxB, 2));
            const float mAn = fmaxf(mA, mxA), mBn = fmaxf(mB, mxB);
            bool changed = (mAn != mA) || (mBn != mB);
            if (__any_sync(0xffffffffu, changed)) {
                const float cA = ex2(mA - mAn), cB = ex2(mB - mBn);
                mA = mAn; mB = mBn;
                lA *= cA; lB *= cB;
#pragma unroll
                for (int nt = 0; nt < 8; nt++) {
                    O[nt][0] *= cA; O[nt][1] *= cA;
                    O[nt][2] *= cB; O[nt][3] *= cB;
                }
            }
#pragma unroll
            for (int nt = 0; nt < 8; nt++) {
                float p0 = to_tf32(ex2(s[nt][0] - mA));
                float p1 = to_tf32(ex2(s[nt][1] - mA));
                float p2 = to_tf32(ex2(s[nt][2] - mB));
                float p3 = to_tf32(ex2(s[nt][3] - mB));
                s[nt][0] = p0; s[nt][1] = p1; s[nt][2] = p2; s[nt][3] = p3;
                lA += p0 + p1; lB += p2 + p3;
            }

            // ---- O += P V (shuffle-free A-frag from QK C-frag) ----
#pragma unroll
            for (int kp = 0; kp < 4; kp++) {
                const int co = ((kp * 4 + q) ^ swz) * 4;
#pragma unroll
                for (int nt = 0; nt < 8; nt++) {
                    float4 vf = *(const float4*)&Vs[(nt * 8 + g) * 64 + co];
                    mma8f(O[nt], s[2 * kp][0], s[2 * kp][2], s[2 * kp][1],
                          s[2 * kp][3], vf.x, vf.y);
                    mma8f(O[nt], s[2 * kp + 1][0], s[2 * kp + 1][2], s[2 * kp + 1][1],
                          s[2 * kp + 1][3], vf.z, vf.w);
                }
            }
        }
        __syncthreads();
    }

    lA += __shfl_xor_sync(0xffffffffu, lA, 1);
    lA += __shfl_xor_sync(0xffffffffu, lA, 2);
    lB += __shfl_xor_sync(0xffffffffu, lB, 1);
    lB += __shfl_xor_sync(0xffffffffu, lB, 2);
    const float invA = 1.0f / lA, invB = 1.0f / lB;
#pragma unroll
    for (int nt = 0; nt < 8; nt++) {
        int col = h * HDIM + nt * 8 + 2 * q;
        *(float2*)&g_attn[(size_t)iA * DMODEL + col] =
            make_float2(to_tf32(O[nt][0] * invA), to_tf32(O[nt][1] * invA));
        *(float2*)&g_attn[(size_t)iB * DMODEL + col] =
            make_float2(to_tf32(O[nt][2] * invB), to_tf32(O[nt][3] * invB));
    }
}

// ---------------------------------------------------------------------------
extern "C" void kernel_launch(void* const* d_in, const int* in_sizes, int n_in,
                              void* d_out, int out_size) {
    const float* x  = (const float*)d_in[0];
    const float* qw = (const float*)d_in[1];
    const float* kw = (const float*)d_in[2];
    const float* vw = (const float*)d_in[3];
    const float* ow = (const float*)d_in[4];
    float* out = (float*)d_out;

    float *pq, *pk, *pv, *pa, *pwt, *pxr;
    cudaGetSymbolAddress((void**)&pq, g_q);
    cudaGetSymbolAddress((void**)&pk, g_k);
    cudaGetSymbolAddress((void**)&pv, g_v);
    cudaGetSymbolAddress((void**)&pa, g_attn);
    cudaGetSymbolAddress((void**)&pwt, g_wt);
    cudaGetSymbolAddress((void**)&pxr, g_xr);

    const int SMEM_ATTN = AT_FLOATS * 4;  // 98304 B
    cudaFuncSetAttribute(gemm_mma<true>,  cudaFuncAttributeMaxDynamicSharedMemorySize, SMEM_GEMM3);
    cudaFuncSetAttribute(gemm_mma<false>, cudaFuncAttributeMaxDynamicSharedMemorySize, SMEM_GEMM3);
    cudaFuncSetAttribute(attn_mma, cudaFuncAttributeMaxDynamicSharedMemorySize, SMEM_ATTN);

    round_x<<<(L_SEQ * DMODEL) / (256 * 4), 256>>>(x, pxr);
    dim3 tb(32, 8);
    dim3 tg(DMODEL / 32, DMODEL / 32, 4);
    transpose_w<<<tg, tb>>>(qw, kw, vw, ow, pwt);

    const float qscale = 0.125f * LOG2E;
    dim3 gqkv(DMODEL / 128, L_SEQ / 128, 3);
    gemm_mma<true><<<gqkv, 256, SMEM_GEMM3>>>(pxr, pwt, pq, pk, pv,
                                              L_SEQ, DMODEL, DMODEL, qscale);

    dim3 ga(L_SEQ / 128, NHEADS);
    attn_mma<<<ga, 256, SMEM_ATTN>>>();

    dim3 gout(DMODEL / 128, L_SEQ / 128, 1);
    gemm_mma<false><<<gout, 256, SMEM_GEMM3>>>(pa, pwt + 3 * (size_t)DMODEL * DMODEL,
                                               out, nullptr, nullptr,
                                               L_SEQ, DMODEL, DMODEL, 1.0f);
}

// round 13
// speedup vs baseline: 1.0551x; 1.0402x over previous
#include <cuda_runtime.h>
#include <math.h>
#include <stdint.h>

#define L_SEQ  4096
#define DMODEL 1024
#define NHEADS 16
#define HDIM   64
#define LOG2E  1.4426950408889634f

// Scratch (allocation-free rule: __device__ globals)
// Layouts: g_q/g_k have the d-dim permuted within 8-groups (perm8) so QK^T
// fragment loads are single LDS.64 (mma k-dim is permutation-invariant when
// both operands agree). g_v is PLAIN transposed [h][d][seq]: the PV mma uses
// the k-ordering slot q <-> key 2q, slot q+4 <-> key 2q+1, under which the
// QK C-fragment IS the PV A-fragment (no shuffles) and a float2 V load at
// 2q gives the matching B-fragment.
__device__ float g_q[NHEADS * L_SEQ * HDIM];   // [h][seq][dperm], *0.125*log2e, tf32
__device__ float g_k[NHEADS * L_SEQ * HDIM];   // [h][seq][dperm], tf32
__device__ float g_v[NHEADS * HDIM * L_SEQ];   // [h][d][seq], tf32
__device__ float g_attn[L_SEQ * DMODEL];       // [seq][dmodel], tf32
__device__ float g_wt[4 * DMODEL * DMODEL];    // transposed tf32 weights [N][K]
__device__ float g_xr[L_SEQ * DMODEL];         // tf32-rounded x

__device__ __forceinline__ uint32_t smem_u32(const void* p) {
    uint32_t a;
    asm("{ .reg .u64 t; cvta.to.shared.u64 t, %1; cvt.u32.u64 %0, t; }" : "=r"(a) : "l"(p));
    return a;
}
__device__ __forceinline__ float to_tf32(float x) {
    uint32_t r; asm("cvt.rna.tf32.f32 %0, %1;" : "=r"(r) : "f"(x));
    return __uint_as_float(r);
}
// cheap RZ truncation to tf32 bit-pattern (single LOP3 on the alu pipe).
// Valid for p in [0,1]: the MMA truncates to these bits anyway; l-sum uses the
// same masked value so numerator/denominator stay consistent.
__device__ __forceinline__ float tf32_trunc(float x) {
    return __uint_as_float(__float_as_uint(x) & 0xffffe000u);
}
__device__ __forceinline__ float ex2(float x) {
    float y; asm("ex2.approx.f32 %0, %1;" : "=f"(y) : "f"(x)); return y;
}
__device__ __forceinline__ int perm8(int l) { return (l < 4) ? (2 * l) : (2 * (l - 4) + 1); }
__device__ __forceinline__ void mma8(float* c, uint32_t a0, uint32_t a1, uint32_t a2,
                                     uint32_t a3, uint32_t b0, uint32_t b1) {
    asm volatile(
        "mma.sync.aligned.m16n8k8.row.col.f32.tf32.tf32.f32 "
        "{%0,%1,%2,%3}, {%4,%5,%6,%7}, {%8,%9}, {%0,%1,%2,%3};"
        : "+f"(c[0]), "+f"(c[1]), "+f"(c[2]), "+f"(c[3])
        : "r"(a0), "r"(a1), "r"(a2), "r"(a3), "r"(b0), "r"(b1));
}

// ---------------------------------------------------------------------------
__global__ __launch_bounds__(256) void round_x(const float* __restrict__ x,
                                               float* __restrict__ xr) {
    int i = (blockIdx.x * 256 + threadIdx.x) * 4;
    float4 v = *(const float4*)&x[i];
    *(float4*)&xr[i] = make_float4(to_tf32(v.x), to_tf32(v.y), to_tf32(v.z), to_tf32(v.w));
}

// ---------------------------------------------------------------------------
__global__ __launch_bounds__(256) void transpose_w(const float* __restrict__ w0,
                                                   const float* __restrict__ w1,
                                                   const float* __restrict__ w2,
                                                   const float* __restrict__ w3,
                                                   float* __restrict__ dst) {
    __shared__ float tile[32][33];
    const int z = blockIdx.z;
    const float* src = (z == 0) ? w0 : (z == 1) ? w1 : (z == 2) ? w2 : w3;
    float* d = dst + (size_t)z * DMODEL * DMODEL;
    const int tx = threadIdx.x, ty = threadIdx.y;
    const int x = blockIdx.x * 32 + tx;
    const int y0 = blockIdx.y * 32;
#pragma unroll
    for (int j = ty; j < 32; j += 8)
        tile[j][tx] = to_tf32(src[(size_t)(y0 + j) * DMODEL + x]);
    __syncthreads();
    const int xo = blockIdx.y * 32 + tx;
    const int yo0 = blockIdx.x * 32;
#pragma unroll
    for (int j = ty; j < 32; j += 8)
        d[(size_t)(yo0 + j) * DMODEL + xo] = tile[tx][j];
}

// ---------------------------------------------------------------------------
// tf32 mma.sync GEMM: CTA 128x128x32, 8 warps, 3-stage cp.async pipeline.
// FUSED: z=0 -> g_q (scaled, d-permuted), z=1 -> g_k (d-permuted),
//        z=2 -> g_v (transposed, plain). All tf32-rounded.
// !FUSED: plain C[row*N+col].
// ---------------------------------------------------------------------------
#define GBK 32
#define STG_FLOATS (128 * 36)
#define SMEM_GEMM3 (3 * 2 * STG_FLOATS * 4)

template <bool FUSED>
__global__ __launch_bounds__(256, 2)
void gemm_mma(const float* __restrict__ A, const float* __restrict__ WtBase,
              float* __restrict__ C0, float* __restrict__ C1, float* __restrict__ C2,
              int M, int N, int K, float qscale) {
    extern __shared__ float smf[];
    const uint32_t sbase = smem_u32(smf);
    const int tid = threadIdx.x;
    const int wid = tid >> 5;
    const int lane = tid & 31;
    const int row0 = blockIdx.y * 128;
    const int col0 = blockIdx.x * 128;
    const int z = FUSED ? (int)blockIdx.z : 0;
    const float* Bt = WtBase + (size_t)z * DMODEL * DMODEL;
    const int wm = (wid & 1) * 64;
    const int wn = (wid >> 1) * 32;
    const int g = lane >> 2;
    const int q = lane & 3;

    const int l_row = tid >> 3;
    const int l_c   = tid & 7;

    float c[4][4][4];
#pragma unroll
    for (int mt = 0; mt < 4; mt++)
#pragma unroll
        for (int nt = 0; nt < 4; nt++)
#pragma unroll
            for (int r = 0; r < 4; r++) c[mt][nt][r] = 0.f;

    auto stage_load = [&](int kb, int s) {
        const int k0 = kb * GBK;
#pragma unroll
        for (int i = 0; i < 4; i++) {
            int r = l_row + i * 32;
            uint32_t da = sbase + (uint32_t)(s * 2 * STG_FLOATS + r * 36 + l_c * 4) * 4u;
            const float* ga = &A[(size_t)(row0 + r) * K + k0 + l_c * 4];
            asm volatile("cp.async.cg.shared.global [%0], [%1], 16;" :: "r"(da), "l"(ga));
            uint32_t db = da + (uint32_t)STG_FLOATS * 4u;
            const float* gb = &Bt[(size_t)(col0 + r) * K + k0 + l_c * 4];
            asm volatile("cp.async.cg.shared.global [%0], [%1], 16;" :: "r"(db), "l"(gb));
        }
        asm volatile("cp.async.commit_group;");
    };

    const int NK = K / GBK;
    stage_load(0, 0);
    stage_load(1, 1);

    int s = 0;
    for (int kb = 0; kb < NK; kb++) {
        if (kb + 1 < NK) {
            asm volatile("cp.async.wait_group 1;");
        } else {
            asm volatile("cp.async.wait_group 0;");
        }
        __syncthreads();
        if (kb + 2 < NK) stage_load(kb + 2, (kb + 2) % 3);

        const float* As = smf + s * 2 * STG_FLOATS;
        const float* Bs = As + STG_FLOATS;
        const float* pa = &As[(wm + g) * 36 + q];
        const float* pb = &Bs[(wn + g) * 36 + q];

#pragma unroll
        for (int ks = 0; ks < 4; ks++) {
            uint32_t af[4][4], bf[4][2];
#pragma unroll
            for (int mt = 0; mt < 4; mt++) {
                af[mt][0] = __float_as_uint(pa[(mt * 16 + 0) * 36 + ks * 8 + 0]);
                af[mt][1] = __float_as_uint(pa[(mt * 16 + 8) * 36 + ks * 8 + 0]);
                af[mt][2] = __float_as_uint(pa[(mt * 16 + 0) * 36 + ks * 8 + 4]);
                af[mt][3] = __float_as_uint(pa[(mt * 16 + 8) * 36 + ks * 8 + 4]);
            }
#pragma unroll
            for (int nt = 0; nt < 4; nt++) {
                bf[nt][0] = __float_as_uint(pb[(nt * 8) * 36 + ks * 8 + 0]);
                bf[nt][1] = __float_as_uint(pb[(nt * 8) * 36 + ks * 8 + 4]);
            }
#pragma unroll
            for (int mt = 0; mt < 4; mt++)
#pragma unroll
                for (int nt = 0; nt < 4; nt++)
                    mma8(c[mt][nt], af[mt][0], af[mt][1], af[mt][2], af[mt][3],
                         bf[nt][0], bf[nt][1]);
        }
        s = (s + 1) % 3;
    }

    const float scale = (FUSED && z == 0) ? qscale : 1.0f;
#pragma unroll
    for (int mt = 0; mt < 4; mt++) {
#pragma unroll
        for (int hr = 0; hr < 2; hr++) {
            int row = row0 + wm + mt * 16 + g + hr * 8;
#pragma unroll
            for (int nt = 0; nt < 4; nt++) {
                int col = col0 + wn + nt * 8 + q * 2;
                float vx = c[mt][nt][hr * 2] * scale;
                float vy = c[mt][nt][hr * 2 + 1] * scale;
                if (!FUSED) {
                    *(float2*)&C0[(size_t)row * N + col] = make_float2(vx, vy);
                } else {
                    vx = to_tf32(vx); vy = to_tf32(vy);
                    int head = col >> 6, d0 = col & 63, d1 = d0 + 1;
                    if (z == 2) {
                        C2[((size_t)(head * 64 + d0)) * M + row] = vx;  // plain transposed
                        C2[((size_t)(head * 64 + d1)) * M + row] = vy;
                    } else {
                        float* C = (z == 0) ? C0 : C1;
                        size_t base = ((size_t)head * M + row) * 64;
                        C[base + ((d0 & ~7) | perm8(d0 & 7))] = vx;  // d permuted
                        C[base + ((d1 & ~7) | perm8(d1 & 7))] = vy;
                    }
                }
            }
        }
    }
}

// ---------------------------------------------------------------------------
// Tensor-core flash attention, diagonal-first tiles, LDS.64 fragment loads,
// shuffle-free P reuse (QK C-frag == PV A-frag under pair-interleaved
// k-ordering), scalar l-sums, LOP3 tf32-truncation of p.
// Block = (head, 128 q-rows), 8 warps x 16 rows. 64-key double-buffered tiles.
// ---------------------------------------------------------------------------
#define PADK 72
#define AT_QOFF   0
#define AT_KOFF   (128 * PADK)
#define AT_VOFF   (AT_KOFF + 2 * 64 * PADK)
#define AT_FLOATS (AT_VOFF + 2 * 64 * PADK)   // 27648 floats = 110592 B

__global__ __launch_bounds__(256, 2) void attn_mma() {
    extern __shared__ float sm[];
    const uint32_t sb = smem_u32(sm);
    const int h  = blockIdx.y;
    const int bx = (int)gridDim.x - 1 - (int)blockIdx.x;  // big tiles first
    const int i0 = bx * 128;
    const int tid = threadIdx.x;
    const int w = tid >> 5;
    const int lane = tid & 31;
    const int g = lane >> 2, q = lane & 3;
    const int qr = w * 16;
    const float slope2 = ex2(-0.5f * (float)(h + 1)) * LOG2E;

    const float* Qs = sm + AT_QOFF;

    auto load_tile = [&](int t, int s) {
        const int j0 = t * 64;
        const float* kp = g_k + ((size_t)h * L_SEQ + j0) * HDIM;
        const float* vp = g_v + (size_t)h * HDIM * L_SEQ + j0;
        const uint32_t kd = sb + (AT_KOFF + s * 64 * PADK) * 4u;
        const uint32_t vd = sb + (AT_VOFF + s * 64 * PADK) * 4u;
#pragma unroll
        for (int i = 0; i < 4; i++) {
            int cc = tid + i * 256;
            int row = cc >> 4, c16 = cc & 15;
            asm volatile("cp.async.cg.shared.global [%0], [%1], 16;"
                         :: "r"(kd + (uint32_t)(row * PADK + c16 * 4) * 4u),
                            "l"(kp + (size_t)row * HDIM + c16 * 4));
            asm volatile("cp.async.cg.shared.global [%0], [%1], 16;"
                         :: "r"(vd + (uint32_t)(row * PADK + c16 * 4) * 4u),
                            "l"(vp + (size_t)row * L_SEQ + c16 * 4));
        }
        asm volatile("cp.async.commit_group;");
    };

    const int ntiles = 2 * bx + 2;
    const int tstart = ntiles - 1;

    {
        const float* qp = g_q + ((size_t)h * L_SEQ + i0) * HDIM;
        const uint32_t qd = sb + AT_QOFF * 4u;
#pragma unroll
        for (int i = 0; i < 8; i++) {
            int cc = tid + i * 256;
            int row = cc >> 4, c16 = cc & 15;
            asm volatile("cp.async.cg.shared.global [%0], [%1], 16;"
                         :: "r"(qd + (uint32_t)(row * PADK + c16 * 4) * 4u),
                            "l"(qp + (size_t)row * HDIM + c16 * 4));
        }
        load_tile(tstart, tstart & 1);
    }

    float mA = -INFINITY, mB = -INFINITY, lA = 0.f, lB = 0.f;
    float O[8][4];
#pragma unroll
    for (int nt = 0; nt < 8; nt++)
#pragma unroll
        for (int r = 0; r < 4; r++) O[nt][r] = 0.f;

    const int iA = i0 + qr + g;
    const int iB = iA + 8;

    for (int t = tstart; t >= 0; t--) {
        if (t > 0) {
            load_tile(t - 1, (t - 1) & 1);
            asm volatile("cp.async.wait_group 1;");
        } else {
            asm volatile("cp.async.wait_group 0;");
        }
        __syncthreads();

        const int j0 = t * 64;
        if (j0 <= i0 + qr + 15) {
            const float* Ks = sm + AT_KOFF + (t & 1) * 64 * PADK;
            const float* Vs = sm + AT_VOFF + (t & 1) * 64 * PADK;

            // ---- S = Q K^T (paired d-layout: LDS.64 frags) ----
            float s[8][4];
#pragma unroll
            for (int nt = 0; nt < 8; nt++)
#pragma unroll
                for (int r = 0; r < 4; r++) s[nt][r] = 0.f;

#pragma unroll
            for (int ks = 0; ks < 8; ks++) {
                float2 qa = *(const float2*)&Qs[(qr + g) * PADK + ks * 8 + 2 * q];
                float2 qb = *(const float2*)&Qs[(qr + g + 8) * PADK + ks * 8 + 2 * q];
                uint32_t a0 = __float_as_uint(qa.x), a2 = __float_as_uint(qa.y);
                uint32_t a1 = __float_as_uint(qb.x), a3 = __float_as_uint(qb.y);
#pragma unroll
                for (int nt = 0; nt < 8; nt++) {
                    float2 kb = *(const float2*)&Ks[(nt * 8 + g) * PADK + ks * 8 + 2 * q];
                    mma8(s[nt], a0, a1, a2, a3,
                         __float_as_uint(kb.x), __float_as_uint(kb.y));
                }
            }

            // ---- ALiBi + causal ----
            const bool needmask = (j0 + 63 > i0 + qr);
#pragma unroll
            for (int nt = 0; nt < 8; nt++) {
                int j = j0 + nt * 8 + 2 * q;
                s[nt][0] -= slope2 * (float)(iA - j);
                s[nt][1] -= slope2 * (float)(iA - j - 1);
                s[nt][2] -= slope2 * (float)(iB - j);
                s[nt][3] -= slope2 * (float)(iB - j - 1);
                if (needmask) {
                    if (j > iA)     s[nt][0] = -INFINITY;
                    if (j + 1 > iA) s[nt][1] = -INFINITY;
                    if (j > iB)     s[nt][2] = -INFINITY;
                    if (j + 1 > iB) s[nt][3] = -INFINITY;
                }
            }

            // ---- online softmax (diagonal-first: rescale rarely fires) ----
            float mxA = -INFINITY, mxB = -INFINITY;
#pragma unroll
            for (int nt = 0; nt < 8; nt++) {
                mxA = fmaxf(mxA, fmaxf(s[nt][0], s[nt][1]));
                mxB = fmaxf(mxB, fmaxf(s[nt][2], s[nt][3]));
            }
            mxA = fmaxf(mxA, __shfl_xor_sync(0xffffffffu, mxA, 1));
            mxA = fmaxf(mxA, __shfl_xor_sync(0xffffffffu, mxA, 2));
            mxB = fmaxf(mxB, __shfl_xor_sync(0xffffffffu, mxB, 1));
            mxB = fmaxf(mxB, __shfl_xor_sync(0xffffffffu, mxB, 2));
            const float mAn = fmaxf(mA, mxA), mBn = fmaxf(mB, mxB);
            bool changed = (mAn != mA) || (mBn != mB);
            if (__any_sync(0xffffffffu, changed)) {
                const float cA = ex2(mA - mAn), cB = ex2(mB - mBn);  // ==1 if unchanged
                mA = mAn; mB = mBn;
                lA *= cA; lB *= cB;
#pragma unroll
                for (int nt = 0; nt < 8; nt++) {
                    O[nt][0] *= cA; O[nt][1] *= cA;
                    O[nt][2] *= cB; O[nt][3] *= cB;
                }
            }
#pragma unroll
            for (int nt = 0; nt < 8; nt++) {
                float p0 = tf32_trunc(ex2(s[nt][0] - mA));
                float p1 = tf32_trunc(ex2(s[nt][1] - mA));
                float p2 = tf32_trunc(ex2(s[nt][2] - mB));
                float p3 = tf32_trunc(ex2(s[nt][3] - mB));
                s[nt][0] = p0; s[nt][1] = p1; s[nt][2] = p2; s[nt][3] = p3;
                lA += p0 + p1; lB += p2 + p3;
            }

            // ---- O += P V : shuffle-free, pair-interleaved k-ordering ----
            // A-frag: a0 = P[row g][key 2q]    = s[ks][0]
            //         a1 = P[row g+8][key 2q]  = s[ks][2]
            //         a2 = P[row g][key 2q+1]  = s[ks][1]
            //         a3 = P[row g+8][key 2q+1]= s[ks][3]
            // B-frag: float2 V load at ks*8+2q -> keys {2q, 2q+1}
#pragma unroll
            for (int ks = 0; ks < 8; ks++) {
                uint32_t a0 = __float_as_uint(s[ks][0]);
                uint32_t a1 = __float_as_uint(s[ks][2]);
                uint32_t a2 = __float_as_uint(s[ks][1]);
                uint32_t a3 = __float_as_uint(s[ks][3]);
#pragma unroll
                for (int nt = 0; nt < 8; nt++) {
                    float2 vb = *(const float2*)&Vs[(nt * 8 + g) * PADK + ks * 8 + 2 * q];
                    mma8(O[nt], a0, a1, a2, a3,
                         __float_as_uint(vb.x), __float_as_uint(vb.y));
                }
            }
        }
        __syncthreads();
    }

    lA += __shfl_xor_sync(0xffffffffu, lA, 1);
    lA += __shfl_xor_sync(0xffffffffu, lA, 2);
    lB += __shfl_xor_sync(0xffffffffu, lB, 1);
    lB += __shfl_xor_sync(0xffffffffu, lB, 2);
    const float invA = 1.0f / lA, invB = 1.0f / lB;
#pragma unroll
    for (int nt = 0; nt < 8; nt++) {
        int col = h * HDIM + nt * 8 + 2 * q;
        *(float2*)&g_attn[(size_t)iA * DMODEL + col] =
            make_float2(to_tf32(O[nt][0] * invA), to_tf32(O[nt][1] * invA));
        *(float2*)&g_attn[(size_t)iB * DMODEL + col] =
            make_float2(to_tf32(O[nt][2] * invB), to_tf32(O[nt][3] * invB));
    }
}

// ---------------------------------------------------------------------------
extern "C" void kernel_launch(void* const* d_in, const int* in_sizes, int n_in,
                              void* d_out, int out_size) {
    const float* x  = (const float*)d_in[0];
    const float* qw = (const float*)d_in[1];
    const float* kw = (const float*)d_in[2];
    const float* vw = (const float*)d_in[3];
    const float* ow = (const float*)d_in[4];
    float* out = (float*)d_out;

    float *pq, *pk, *pv, *pa, *pwt, *pxr;
    cudaGetSymbolAddress((void**)&pq, g_q);
    cudaGetSymbolAddress((void**)&pk, g_k);
    cudaGetSymbolAddress((void**)&pv, g_v);
    cudaGetSymbolAddress((void**)&pa, g_attn);
    cudaGetSymbolAddress((void**)&pwt, g_wt);
    cudaGetSymbolAddress((void**)&pxr, g_xr);

    const int SMEM_ATTN = AT_FLOATS * 4;  // 110592 B
    cudaFuncSetAttribute(gemm_mma<true>,  cudaFuncAttributeMaxDynamicSharedMemorySize, SMEM_GEMM3);
    cudaFuncSetAttribute(gemm_mma<false>, cudaFuncAttributeMaxDynamicSharedMemorySize, SMEM_GEMM3);
    cudaFuncSetAttribute(attn_mma, cudaFuncAttributeMaxDynamicSharedMemorySize, SMEM_ATTN);

    round_x<<<(L_SEQ * DMODEL) / (256 * 4), 256>>>(x, pxr);
    dim3 tb(32, 8);
    dim3 tg(DMODEL / 32, DMODEL / 32, 4);
    transpose_w<<<tg, tb>>>(qw, kw, vw, ow, pwt);

    const float qscale = 0.125f * LOG2E;
    dim3 gqkv(DMODEL / 128, L_SEQ / 128, 3);
    gemm_mma<true><<<gqkv, 256, SMEM_GEMM3>>>(pxr, pwt, pq, pk, pv,
                                              L_SEQ, DMODEL, DMODEL, qscale);

    dim3 ga(L_SEQ / 128, NHEADS);
    attn_mma<<<ga, 256, SMEM_ATTN>>>();

    dim3 gout(DMODEL / 128, L_SEQ / 128, 1);
    gemm_mma<false><<<gout, 256, SMEM_GEMM3>>>(pa, pwt + 3 * (size_t)DMODEL * DMODEL,
                                               out, nullptr, nullptr,
                                               L_SEQ, DMODEL, DMODEL, 1.0f);
}

// round 14
// speedup vs baseline: 1.0963x; 1.0390x over previous
#include <cuda_runtime.h>
#include <math.h>
#include <stdint.h>

#define L_SEQ  4096
#define DMODEL 1024
#define NHEADS 16
#define HDIM   64
#define LOG2E  1.4426950408889634f

// Scratch (allocation-free rule: __device__ globals)
// Layouts (mma k-dim permutation-invariant when both operands agree):
//  * g_q/g_k: head-d dim pair-interleaved (perm8) -> attention QK frags = LDS.64
//  * g_v: plain transposed [h][d][seq] (QK C-frag == PV A-frag ordering)
//  * g_xr/g_wt/g_attn: DMODEL k-dim pair-interleaved (perm8) -> GEMM frags = LDS.64
__device__ float g_q[NHEADS * L_SEQ * HDIM];   // [h][seq][dperm], *0.125*log2e, tf32
__device__ float g_k[NHEADS * L_SEQ * HDIM];   // [h][seq][dperm], tf32
__device__ float g_v[NHEADS * HDIM * L_SEQ];   // [h][d][seq], tf32
__device__ float g_attn[L_SEQ * DMODEL];       // [seq][kperm], tf32
__device__ float g_wt[4 * DMODEL * DMODEL];    // transposed tf32 weights [N][Kperm]
__device__ float g_xr[L_SEQ * DMODEL];         // tf32-rounded x, [seq][kperm]

__device__ __forceinline__ uint32_t smem_u32(const void* p) {
    uint32_t a;
    asm("{ .reg .u64 t; cvta.to.shared.u64 t, %1; cvt.u32.u64 %0, t; }" : "=r"(a) : "l"(p));
    return a;
}
__device__ __forceinline__ float to_tf32(float x) {
    uint32_t r; asm("cvt.rna.tf32.f32 %0, %1;" : "=r"(r) : "f"(x));
    return __uint_as_float(r);
}
// cheap RZ truncation to tf32 bit-pattern (single LOP3 on the alu pipe)
__device__ __forceinline__ float tf32_trunc(float x) {
    return __uint_as_float(__float_as_uint(x) & 0xffffe000u);
}
__device__ __forceinline__ float ex2(float x) {
    float y; asm("ex2.approx.f32 %0, %1;" : "=f"(y) : "f"(x)); return y;
}
// logical slot l (0..7) -> physical position in pair-interleaved 8-group
__device__ __forceinline__ int perm8(int l) { return (l < 4) ? (2 * l) : (2 * (l - 4) + 1); }
__device__ __forceinline__ void mma8(float* c, uint32_t a0, uint32_t a1, uint32_t a2,
                                     uint32_t a3, uint32_t b0, uint32_t b1) {
    asm volatile(
        "mma.sync.aligned.m16n8k8.row.col.f32.tf32.tf32.f32 "
        "{%0,%1,%2,%3}, {%4,%5,%6,%7}, {%8,%9}, {%0,%1,%2,%3};"
        : "+f"(c[0]), "+f"(c[1]), "+f"(c[2]), "+f"(c[3])
        : "r"(a0), "r"(a1), "r"(a2), "r"(a3), "r"(b0), "r"(b1));
}
__device__ __forceinline__ void mma8f(float* c, float a0, float a1, float a2,
                                      float a3, float b0, float b1) {
    mma8(c, __float_as_uint(a0), __float_as_uint(a1), __float_as_uint(a2),
         __float_as_uint(a3), __float_as_uint(b0), __float_as_uint(b1));
}

// ---------------------------------------------------------------------------
// Round x to tf32 AND pair-interleave each 8-float k-group:
// phys chunk0 = (l0,l4,l1,l5), chunk1 = (l2,l6,l3,l7). Still 2x STG.128.
// ---------------------------------------------------------------------------
__global__ __launch_bounds__(256) void round_x(const float* __restrict__ x,
                                               float* __restrict__ xr) {
    int i = (blockIdx.x * 256 + threadIdx.x) * 8;
    float4 a = *(const float4*)&x[i];
    float4 b = *(const float4*)&x[i + 4];
    *(float4*)&xr[i] =
        make_float4(to_tf32(a.x), to_tf32(b.x), to_tf32(a.y), to_tf32(b.y));
    *(float4*)&xr[i + 4] =
        make_float4(to_tf32(a.z), to_tf32(b.z), to_tf32(a.w), to_tf32(b.w));
}

// ---------------------------------------------------------------------------
// Weight transpose + tf32 rounding + k-dim pair-interleave: W[K][N] -> Wt[N][Kperm]
// ---------------------------------------------------------------------------
__global__ __launch_bounds__(256) void transpose_w(const float* __restrict__ w0,
                                                   const float* __restrict__ w1,
                                                   const float* __restrict__ w2,
                                                   const float* __restrict__ w3,
                                                   float* __restrict__ dst) {
    __shared__ float tile[32][33];
    const int z = blockIdx.z;
    const float* src = (z == 0) ? w0 : (z == 1) ? w1 : (z == 2) ? w2 : w3;
    float* d = dst + (size_t)z * DMODEL * DMODEL;
    const int tx = threadIdx.x, ty = threadIdx.y;
    const int x = blockIdx.x * 32 + tx;
    const int y0 = blockIdx.y * 32;
#pragma unroll
    for (int j = ty; j < 32; j += 8)
        tile[j][tx] = to_tf32(src[(size_t)(y0 + j) * DMODEL + x]);
    __syncthreads();
    const int xo_l = blockIdx.y * 32 + tx;               // logical k index
    const int xo = (xo_l & ~7) | perm8(xo_l & 7);        // pair-interleaved
    const int yo0 = blockIdx.x * 32;
#pragma unroll
    for (int j = ty; j < 32; j += 8)
        d[(size_t)(yo0 + j) * DMODEL + xo] = tile[tx][j];
}

// ---------------------------------------------------------------------------
// tf32 mma.sync GEMM: CTA 128x128x32, 8 warps, 3-stage cp.async pipeline.
// Global k-layout is pair-interleaved; smem stage is 128 rows x 32 floats with
// an 8-float-group XOR swizzle (group ^ (row&3)) -> LDS.64 fragment loads,
// conflict-free, zero per-load address ALU (swizzle folds into unrolled ks).
// FUSED: z=0 -> g_q (scaled, head-d perm8), z=1 -> g_k (head-d perm8),
//        z=2 -> g_v (plain transposed). All tf32-rounded.
// !FUSED: plain C[row*N+col].
// ---------------------------------------------------------------------------
#define GBK 32
#define STG_FLOATS (128 * 32)
#define SMEM_GEMM3 (3 * 2 * STG_FLOATS * 4)   // 98304 B

template <bool FUSED>
__global__ __launch_bounds__(256, 2)
void gemm_mma(const float* __restrict__ A, const float* __restrict__ WtBase,
              float* __restrict__ C0, float* __restrict__ C1, float* __restrict__ C2,
              int M, int N, int K, float qscale) {
    extern __shared__ float smf[];
    const uint32_t sbase = smem_u32(smf);
    const int tid = threadIdx.x;
    const int wid = tid >> 5;
    const int lane = tid & 31;
    const int row0 = blockIdx.y * 128;
    const int col0 = blockIdx.x * 128;
    const int z = FUSED ? (int)blockIdx.z : 0;
    const float* Bt = WtBase + (size_t)z * DMODEL * DMODEL;
    const int wm = (wid & 1) * 64;
    const int wn = (wid >> 1) * 32;
    const int g = lane >> 2;
    const int q = lane & 3;

    const int l_row = tid >> 3;       // + 32*i
    const int l_c   = tid & 7;        // 16B chunk index within row
    // swizzled store column offset (row&3 is i-invariant: 32 ≡ 0 mod 4)
    const uint32_t c_off =
        (uint32_t)((((l_c >> 1) ^ (l_row & 3)) << 3) + ((l_c & 1) << 2)) * 4u;

    float c[4][4][4];
#pragma unroll
    for (int mt = 0; mt < 4; mt++)
#pragma unroll
        for (int nt = 0; nt < 4; nt++)
#pragma unroll
            for (int r = 0; r < 4; r++) c[mt][nt][r] = 0.f;

    auto stage_load = [&](int kb, int s) {
        const int k0 = kb * GBK;
#pragma unroll
        for (int i = 0; i < 4; i++) {
            int r = l_row + i * 32;
            uint32_t da = sbase + (uint32_t)(s * 2 * STG_FLOATS + r * 32) * 4u + c_off;
            const float* ga = &A[(size_t)(row0 + r) * K + k0 + l_c * 4];
            asm volatile("cp.async.cg.shared.global [%0], [%1], 16;" :: "r"(da), "l"(ga));
            uint32_t db = da + (uint32_t)STG_FLOATS * 4u;
            const float* gb = &Bt[(size_t)(col0 + r) * K + k0 + l_c * 4];
            asm volatile("cp.async.cg.shared.global [%0], [%1], 16;" :: "r"(db), "l"(gb));
        }
        asm volatile("cp.async.commit_group;");
    };

    const int NK = K / GBK;
    stage_load(0, 0);
    stage_load(1, 1);

    const int rca = (wm + g) & 3;
    const int rcb = (wn + g) & 3;

    int s = 0;
    for (int kb = 0; kb < NK; kb++) {
        if (kb + 1 < NK) {
            asm volatile("cp.async.wait_group 1;");
        } else {
            asm volatile("cp.async.wait_group 0;");
        }
        __syncthreads();
        if (kb + 2 < NK) stage_load(kb + 2, (kb + 2) % 3);

        const float* As = smf + s * 2 * STG_FLOATS;
        const float* Bs = As + STG_FLOATS;
        const float* pa = &As[(wm + g) * 32 + 2 * q];
        const float* pb = &Bs[(wn + g) * 32 + 2 * q];

#pragma unroll
        for (int ks = 0; ks < 4; ks++) {
            const int ca = (ks ^ rca) << 3;
            const int cb = (ks ^ rcb) << 3;
            float2 a02[4], a13[4], b01[4];
#pragma unroll
            for (int mt = 0; mt < 4; mt++) {
                a02[mt] = *(const float2*)&pa[(mt * 16) * 32 + ca];       // (a0, a2)
                a13[mt] = *(const float2*)&pa[(mt * 16 + 8) * 32 + ca];   // (a1, a3)
            }
#pragma unroll
            for (int nt = 0; nt < 4; nt++)
                b01[nt] = *(const float2*)&pb[(nt * 8) * 32 + cb];        // (b0, b1)
#pragma unroll
            for (int mt = 0; mt < 4; mt++)
#pragma unroll
                for (int nt = 0; nt < 4; nt++)
                    mma8f(c[mt][nt], a02[mt].x, a13[mt].x, a02[mt].y, a13[mt].y,
                          b01[nt].x, b01[nt].y);
        }
        s = (s + 1) % 3;
    }

    const float scale = (FUSED && z == 0) ? qscale : 1.0f;
#pragma unroll
    for (int mt = 0; mt < 4; mt++) {
#pragma unroll
        for (int hr = 0; hr < 2; hr++) {
            int row = row0 + wm + mt * 16 + g + hr * 8;
#pragma unroll
            for (int nt = 0; nt < 4; nt++) {
                int col = col0 + wn + nt * 8 + q * 2;
                float vx = c[mt][nt][hr * 2] * scale;
                float vy = c[mt][nt][hr * 2 + 1] * scale;
                if (!FUSED) {
                    *(float2*)&C0[(size_t)row * N + col] = make_float2(vx, vy);
                } else {
                    vx = to_tf32(vx); vy = to_tf32(vy);
                    int head = col >> 6, d0 = col & 63, d1 = d0 + 1;
                    if (z == 2) {
                        C2[((size_t)(head * 64 + d0)) * M + row] = vx;  // plain transposed
                        C2[((size_t)(head * 64 + d1)) * M + row] = vy;
                    } else {
                        float* C = (z == 0) ? C0 : C1;
                        size_t base = ((size_t)head * M + row) * 64;
                        C[base + ((d0 & ~7) | perm8(d0 & 7))] = vx;  // head-d permuted
                        C[base + ((d1 & ~7) | perm8(d1 & 7))] = vy;
                    }
                }
            }
        }
    }
}

// ---------------------------------------------------------------------------
// Tensor-core flash attention (unchanged from R13 except g_attn epilogue
// writes the DMODEL k-dim pair-interleaved for the out-GEMM).
// ---------------------------------------------------------------------------
#define PADK 72
#define AT_QOFF   0
#define AT_KOFF   (128 * PADK)
#define AT_VOFF   (AT_KOFF + 2 * 64 * PADK)
#define AT_FLOATS (AT_VOFF + 2 * 64 * PADK)   // 27648 floats = 110592 B

__global__ __launch_bounds__(256, 2) void attn_mma() {
    extern __shared__ float sm[];
    const uint32_t sb = smem_u32(sm);
    const int h  = blockIdx.y;
    const int bx = (int)gridDim.x - 1 - (int)blockIdx.x;  // big tiles first
    const int i0 = bx * 128;
    const int tid = threadIdx.x;
    const int w = tid >> 5;
    const int lane = tid & 31;
    const int g = lane >> 2, q = lane & 3;
    const int qr = w * 16;
    const float slope2 = ex2(-0.5f * (float)(h + 1)) * LOG2E;

    const float* Qs = sm + AT_QOFF;

    auto load_tile = [&](int t, int s) {
        const int j0 = t * 64;
        const float* kp = g_k + ((size_t)h * L_SEQ + j0) * HDIM;
        const float* vp = g_v + (size_t)h * HDIM * L_SEQ + j0;
        const uint32_t kd = sb + (AT_KOFF + s * 64 * PADK) * 4u;
        const uint32_t vd = sb + (AT_VOFF + s * 64 * PADK) * 4u;
#pragma unroll
        for (int i = 0; i < 4; i++) {
            int cc = tid + i * 256;
            int row = cc >> 4, c16 = cc & 15;
            asm volatile("cp.async.cg.shared.global [%0], [%1], 16;"
                         :: "r"(kd + (uint32_t)(row * PADK + c16 * 4) * 4u),
                            "l"(kp + (size_t)row * HDIM + c16 * 4));
            asm volatile("cp.async.cg.shared.global [%0], [%1], 16;"
                         :: "r"(vd + (uint32_t)(row * PADK + c16 * 4) * 4u),
                            "l"(vp + (size_t)row * L_SEQ + c16 * 4));
        }
        asm volatile("cp.async.commit_group;");
    };

    const int ntiles = 2 * bx + 2;
    const int tstart = ntiles - 1;

    {
        const float* qp = g_q + ((size_t)h * L_SEQ + i0) * HDIM;
        const uint32_t qd = sb + AT_QOFF * 4u;
#pragma unroll
        for (int i = 0; i < 8; i++) {
            int cc = tid + i * 256;
            int row = cc >> 4, c16 = cc & 15;
            asm volatile("cp.async.cg.shared.global [%0], [%1], 16;"
                         :: "r"(qd + (uint32_t)(row * PADK + c16 * 4) * 4u),
                            "l"(qp + (size_t)row * HDIM + c16 * 4));
        }
        load_tile(tstart, tstart & 1);
    }

    float mA = -INFINITY, mB = -INFINITY, lA = 0.f, lB = 0.f;
    float O[8][4];
#pragma unroll
    for (int nt = 0; nt < 8; nt++)
#pragma unroll
        for (int r = 0; r < 4; r++) O[nt][r] = 0.f;

    const int iA = i0 + qr + g;
    const int iB = iA + 8;

    for (int t = tstart; t >= 0; t--) {
        if (t > 0) {
            load_tile(t - 1, (t - 1) & 1);
            asm volatile("cp.async.wait_group 1;");
        } else {
            asm volatile("cp.async.wait_group 0;");
        }
        __syncthreads();

        const int j0 = t * 64;
        if (j0 <= i0 + qr + 15) {
            const float* Ks = sm + AT_KOFF + (t & 1) * 64 * PADK;
            const float* Vs = sm + AT_VOFF + (t & 1) * 64 * PADK;

            // ---- S = Q K^T (paired d-layout: LDS.64 frags) ----
            float s[8][4];
#pragma unroll
            for (int nt = 0; nt < 8; nt++)
#pragma unroll
                for (int r = 0; r < 4; r++) s[nt][r] = 0.f;

#pragma unroll
            for (int ks = 0; ks < 8; ks++) {
                float2 qa = *(const float2*)&Qs[(qr + g) * PADK + ks * 8 + 2 * q];
                float2 qb = *(const float2*)&Qs[(qr + g + 8) * PADK + ks * 8 + 2 * q];
                uint32_t a0 = __float_as_uint(qa.x), a2 = __float_as_uint(qa.y);
                uint32_t a1 = __float_as_uint(qb.x), a3 = __float_as_uint(qb.y);
#pragma unroll
                for (int nt = 0; nt < 8; nt++) {
                    float2 kb = *(const float2*)&Ks[(nt * 8 + g) * PADK + ks * 8 + 2 * q];
                    mma8(s[nt], a0, a1, a2, a3,
                         __float_as_uint(kb.x), __float_as_uint(kb.y));
                }
            }

            // ---- ALiBi + causal ----
            const bool needmask = (j0 + 63 > i0 + qr);
#pragma unroll
            for (int nt = 0; nt < 8; nt++) {
                int j = j0 + nt * 8 + 2 * q;
                s[nt][0] -= slope2 * (float)(iA - j);
                s[nt][1] -= slope2 * (float)(iA - j - 1);
                s[nt][2] -= slope2 * (float)(iB - j);
                s[nt][3] -= slope2 * (float)(iB - j - 1);
                if (needmask) {
                    if (j > iA)     s[nt][0] = -INFINITY;
                    if (j + 1 > iA) s[nt][1] = -INFINITY;
                    if (j > iB)     s[nt][2] = -INFINITY;
                    if (j + 1 > iB) s[nt][3] = -INFINITY;
                }
            }

            // ---- online softmax (diagonal-first: rescale rarely fires) ----
            float mxA = -INFINITY, mxB = -INFINITY;
#pragma unroll
            for (int nt = 0; nt < 8; nt++) {
                mxA = fmaxf(mxA, fmaxf(s[nt][0], s[nt][1]));
                mxB = fmaxf(mxB, fmaxf(s[nt][2], s[nt][3]));
            }
            mxA = fmaxf(mxA, __shfl_xor_sync(0xffffffffu, mxA, 1));
            mxA = fmaxf(mxA, __shfl_xor_sync(0xffffffffu, mxA, 2));
            mxB = fmaxf(mxB, __shfl_xor_sync(0xffffffffu, mxB, 1));
            mxB = fmaxf(mxB, __shfl_xor_sync(0xffffffffu, mxB, 2));
            const float mAn = fmaxf(mA, mxA), mBn = fmaxf(mB, mxB);
            bool changed = (mAn != mA) || (mBn != mB);
            if (__any_sync(0xffffffffu, changed)) {
                const float cA = ex2(mA - mAn), cB = ex2(mB - mBn);
                mA = mAn; mB = mBn;
                lA *= cA; lB *= cB;
#pragma unroll
                for (int nt = 0; nt < 8; nt++) {
                    O[nt][0] *= cA; O[nt][1] *= cA;
                    O[nt][2] *= cB; O[nt][3] *= cB;
                }
            }
#pragma unroll
            for (int nt = 0; nt < 8; nt++) {
                float p0 = tf32_trunc(ex2(s[nt][0] - mA));
                float p1 = tf32_trunc(ex2(s[nt][1] - mA));
                float p2 = tf32_trunc(ex2(s[nt][2] - mB));
                float p3 = tf32_trunc(ex2(s[nt][3] - mB));
                s[nt][0] = p0; s[nt][1] = p1; s[nt][2] = p2; s[nt][3] = p3;
                lA += p0 + p1; lB += p2 + p3;
            }

            // ---- O += P V : shuffle-free, pair-interleaved k-ordering ----
#pragma unroll
            for (int ks = 0; ks < 8; ks++) {
                uint32_t a0 = __float_as_uint(s[ks][0]);
                uint32_t a1 = __float_as_uint(s[ks][2]);
                uint32_t a2 = __float_as_uint(s[ks][1]);
                uint32_t a3 = __float_as_uint(s[ks][3]);
#pragma unroll
                for (int nt = 0; nt < 8; nt++) {
                    float2 vb = *(const float2*)&Vs[(nt * 8 + g) * PADK + ks * 8 + 2 * q];
                    mma8(O[nt], a0, a1, a2, a3,
                         __float_as_uint(vb.x), __float_as_uint(vb.y));
                }
            }
        }
        __syncthreads();
    }

    lA += __shfl_xor_sync(0xffffffffu, lA, 1);
    lA += __shfl_xor_sync(0xffffffffu, lA, 2);
    lB += __shfl_xor_sync(0xffffffffu, lB, 1);
    lB += __shfl_xor_sync(0xffffffffu, lB, 2);
    const float invA = 1.0f / lA, invB = 1.0f / lB;
    // write g_attn with DMODEL-k pair-interleave (for the out-GEMM)
    const int p0 = perm8(2 * q), p1 = perm8(2 * q + 1);
#pragma unroll
    for (int nt = 0; nt < 8; nt++) {
        int colb = h * HDIM + nt * 8;
        g_attn[(size_t)iA * DMODEL + colb + p0] = to_tf32(O[nt][0] * invA);
        g_attn[(size_t)iA * DMODEL + colb + p1] = to_tf32(O[nt][1] * invA);
        g_attn[(size_t)iB * DMODEL + colb + p0] = to_tf32(O[nt][2] * invB);
        g_attn[(size_t)iB * DMODEL + colb + p1] = to_tf32(O[nt][3] * invB);
    }
}

// ---------------------------------------------------------------------------
extern "C" void kernel_launch(void* const* d_in, const int* in_sizes, int n_in,
                              void* d_out, int out_size) {
    const float* x  = (const float*)d_in[0];
    const float* qw = (const float*)d_in[1];
    const float* kw = (const float*)d_in[2];
    const float* vw = (const float*)d_in[3];
    const float* ow = (const float*)d_in[4];
    float* out = (float*)d_out;

    float *pq, *pk, *pv, *pa, *pwt, *pxr;
    cudaGetSymbolAddress((void**)&pq, g_q);
    cudaGetSymbolAddress((void**)&pk, g_k);
    cudaGetSymbolAddress((void**)&pv, g_v);
    cudaGetSymbolAddress((void**)&pa, g_attn);
    cudaGetSymbolAddress((void**)&pwt, g_wt);
    cudaGetSymbolAddress((void**)&pxr, g_xr);

    const int SMEM_ATTN = AT_FLOATS * 4;  // 110592 B
    cudaFuncSetAttribute(gemm_mma<true>,  cudaFuncAttributeMaxDynamicSharedMemorySize, SMEM_GEMM3);
    cudaFuncSetAttribute(gemm_mma<false>, cudaFuncAttributeMaxDynamicSharedMemorySize, SMEM_GEMM3);
    cudaFuncSetAttribute(attn_mma, cudaFuncAttributeMaxDynamicSharedMemorySize, SMEM_ATTN);

    round_x<<<(L_SEQ * DMODEL) / (256 * 8), 256>>>(x, pxr);
    dim3 tb(32, 8);
    dim3 tg(DMODEL / 32, DMODEL / 32, 4);
    transpose_w<<<tg, tb>>>(qw, kw, vw, ow, pwt);

    const float qscale = 0.125f * LOG2E;
    dim3 gqkv(DMODEL / 128, L_SEQ / 128, 3);
    gemm_mma<true><<<gqkv, 256, SMEM_GEMM3>>>(pxr, pwt, pq, pk, pv,
                                              L_SEQ, DMODEL, DMODEL, qscale);

    dim3 ga(L_SEQ / 128, NHEADS);
    attn_mma<<<ga, 256, SMEM_ATTN>>>();

    dim3 gout(DMODEL / 128, L_SEQ / 128, 1);
    gemm_mma<false><<<gout, 256, SMEM_GEMM3>>>(pa, pwt + 3 * (size_t)DMODEL * DMODEL,
                                               out, nullptr, nullptr,
                                               L_SEQ, DMODEL, DMODEL, 1.0f);
}

// round 15
// speedup vs baseline: 1.2718x; 1.1601x over previous
#include <cuda_runtime.h>
#include <math.h>
#include <stdint.h>

#define L_SEQ  4096
#define DMODEL 1024
#define NHEADS 16
#define HDIM   64
#define LOG2E  1.4426950408889634f

// Scratch (allocation-free rule: __device__ globals)
// Layouts (mma k-dim permutation-invariant when both operands agree):
//  * g_q/g_k: head-d dim pair-interleaved (perm8) -> attention QK frags = LDS.64
//  * g_v: plain transposed [h][d][seq] (QK C-frag == PV A-frag ordering)
//  * g_xr/g_wt/g_attn: DMODEL k-dim pair-interleaved (perm8) -> GEMM frags = LDS.64
__device__ float g_q[NHEADS * L_SEQ * HDIM];   // [h][seq][dperm], *0.125*log2e, tf32
__device__ float g_k[NHEADS * L_SEQ * HDIM];   // [h][seq][dperm], tf32
__device__ float g_v[NHEADS * HDIM * L_SEQ];   // [h][d][seq], tf32
__device__ float g_attn[L_SEQ * DMODEL];       // [seq][kperm], tf32
__device__ float g_wt[4 * DMODEL * DMODEL];    // transposed tf32 weights [N][Kperm]
__device__ float g_xr[L_SEQ * DMODEL];         // tf32-rounded x, [seq][kperm]

__device__ __forceinline__ uint32_t smem_u32(const void* p) {
    uint32_t a;
    asm("{ .reg .u64 t; cvta.to.shared.u64 t, %1; cvt.u32.u64 %0, t; }" : "=r"(a) : "l"(p));
    return a;
}
__device__ __forceinline__ float to_tf32(float x) {
    uint32_t r; asm("cvt.rna.tf32.f32 %0, %1;" : "=r"(r) : "f"(x));
    return __uint_as_float(r);
}
// cheap RZ truncation to tf32 bit-pattern (single LOP3 on the alu pipe)
__device__ __forceinline__ float tf32_trunc(float x) {
    return __uint_as_float(__float_as_uint(x) & 0xffffe000u);
}
__device__ __forceinline__ float ex2(float x) {
    float y; asm("ex2.approx.f32 %0, %1;" : "=f"(y) : "f"(x)); return y;
}
// logical slot l (0..7) -> physical position in pair-interleaved 8-group
__device__ __forceinline__ int perm8(int l) { return (l < 4) ? (2 * l) : (2 * (l - 4) + 1); }
__device__ __forceinline__ void mma8(float* c, uint32_t a0, uint32_t a1, uint32_t a2,
                                     uint32_t a3, uint32_t b0, uint32_t b1) {
    asm volatile(
        "mma.sync.aligned.m16n8k8.row.col.f32.tf32.tf32.f32 "
        "{%0,%1,%2,%3}, {%4,%5,%6,%7}, {%8,%9}, {%0,%1,%2,%3};"
        : "+f"(c[0]), "+f"(c[1]), "+f"(c[2]), "+f"(c[3])
        : "r"(a0), "r"(a1), "r"(a2), "r"(a3), "r"(b0), "r"(b1));
}
__device__ __forceinline__ void mma8f(float* c, float a0, float a1, float a2,
                                      float a3, float b0, float b1) {
    mma8(c, __float_as_uint(a0), __float_as_uint(a1), __float_as_uint(a2),
         __float_as_uint(a3), __float_as_uint(b0), __float_as_uint(b1));
}

// ---------------------------------------------------------------------------
// Round x to tf32 AND pair-interleave each 8-float k-group.
// ---------------------------------------------------------------------------
__global__ __launch_bounds__(256) void round_x(const float* __restrict__ x,
                                               float* __restrict__ xr) {
    int i = (blockIdx.x * 256 + threadIdx.x) * 8;
    float4 a = *(const float4*)&x[i];
    float4 b = *(const float4*)&x[i + 4];
    *(float4*)&xr[i] =
        make_float4(to_tf32(a.x), to_tf32(b.x), to_tf32(a.y), to_tf32(b.y));
    *(float4*)&xr[i + 4] =
        make_float4(to_tf32(a.z), to_tf32(b.z), to_tf32(a.w), to_tf32(b.w));
}

// ---------------------------------------------------------------------------
// Weight transpose + tf32 rounding + k-dim pair-interleave: W[K][N] -> Wt[N][Kperm]
// ---------------------------------------------------------------------------
__global__ __launch_bounds__(256) void transpose_w(const float* __restrict__ w0,
                                                   const float* __restrict__ w1,
                                                   const float* __restrict__ w2,
                                                   const float* __restrict__ w3,
                                                   float* __restrict__ dst) {
    __shared__ float tile[32][33];
    const int z = blockIdx.z;
    const float* src = (z == 0) ? w0 : (z == 1) ? w1 : (z == 2) ? w2 : w3;
    float* d = dst + (size_t)z * DMODEL * DMODEL;
    const int tx = threadIdx.x, ty = threadIdx.y;
    const int x = blockIdx.x * 32 + tx;
    const int y0 = blockIdx.y * 32;
#pragma unroll
    for (int j = ty; j < 32; j += 8)
        tile[j][tx] = to_tf32(src[(size_t)(y0 + j) * DMODEL + x]);
    __syncthreads();
    const int xo_l = blockIdx.y * 32 + tx;               // logical k index
    const int xo = (xo_l & ~7) | perm8(xo_l & 7);        // pair-interleaved
    const int yo0 = blockIdx.x * 32;
#pragma unroll
    for (int j = ty; j < 32; j += 8)
        d[(size_t)(yo0 + j) * DMODEL + xo] = tile[tx][j];
}

// ---------------------------------------------------------------------------
// tf32 mma.sync GEMM: CTA 128x128x32, 8 warps, 3-stage cp.async pipeline.
// Global k-layout is pair-interleaved; smem stage is 128 rows x 32 floats with
// an 8-float-group XOR swizzle (group ^ (row&3)) -> LDS.64 fragment loads.
// FUSED: z=0 -> g_q (scaled, head-d perm8), z=1 -> g_k (head-d perm8),
//        z=2 -> g_v (plain transposed). All tf32-rounded.
// !FUSED: plain C[row*N+col].
// ---------------------------------------------------------------------------
#define GBK 32
#define STG_FLOATS (128 * 32)
#define SMEM_GEMM3 (3 * 2 * STG_FLOATS * 4)   // 98304 B

template <bool FUSED>
__global__ __launch_bounds__(256, 2)
void gemm_mma(const float* __restrict__ A, const float* __restrict__ WtBase,
              float* __restrict__ C0, float* __restrict__ C1, float* __restrict__ C2,
              int M, int N, int K, float qscale) {
    extern __shared__ float smf[];
    const uint32_t sbase = smem_u32(smf);
    const int tid = threadIdx.x;
    const int wid = tid >> 5;
    const int lane = tid & 31;
    const int row0 = blockIdx.y * 128;
    const int col0 = blockIdx.x * 128;
    const int z = FUSED ? (int)blockIdx.z : 0;
    const float* Bt = WtBase + (size_t)z * DMODEL * DMODEL;
    const int wm = (wid & 1) * 64;
    const int wn = (wid >> 1) * 32;
    const int g = lane >> 2;
    const int q = lane & 3;

    const int l_row = tid >> 3;       // + 32*i
    const int l_c   = tid & 7;        // 16B chunk index within row
    const uint32_t c_off =
        (uint32_t)((((l_c >> 1) ^ (l_row & 3)) << 3) + ((l_c & 1) << 2)) * 4u;

    float c[4][4][4];
#pragma unroll
    for (int mt = 0; mt < 4; mt++)
#pragma unroll
        for (int nt = 0; nt < 4; nt++)
#pragma unroll
            for (int r = 0; r < 4; r++) c[mt][nt][r] = 0.f;

    auto stage_load = [&](int kb, int s) {
        const int k0 = kb * GBK;
#pragma unroll
        for (int i = 0; i < 4; i++) {
            int r = l_row + i * 32;
            uint32_t da = sbase + (uint32_t)(s * 2 * STG_FLOATS + r * 32) * 4u + c_off;
            const float* ga = &A[(size_t)(row0 + r) * K + k0 + l_c * 4];
            asm volatile("cp.async.cg.shared.global [%0], [%1], 16;" :: "r"(da), "l"(ga));
            uint32_t db = da + (uint32_t)STG_FLOATS * 4u;
            const float* gb = &Bt[(size_t)(col0 + r) * K + k0 + l_c * 4];
            asm volatile("cp.async.cg.shared.global [%0], [%1], 16;" :: "r"(db), "l"(gb));
        }
        asm volatile("cp.async.commit_group;");
    };

    const int NK = K / GBK;
    stage_load(0, 0);
    stage_load(1, 1);

    const int rca = (wm + g) & 3;
    const int rcb = (wn + g) & 3;

    int s = 0;
    for (int kb = 0; kb < NK; kb++) {
        if (kb + 1 < NK) {
            asm volatile("cp.async.wait_group 1;");
        } else {
            asm volatile("cp.async.wait_group 0;");
        }
        __syncthreads();
        if (kb + 2 < NK) stage_load(kb + 2, (kb + 2) % 3);

        const float* As = smf + s * 2 * STG_FLOATS;
        const float* Bs = As + STG_FLOATS;
        const float* pa = &As[(wm + g) * 32 + 2 * q];
        const float* pb = &Bs[(wn + g) * 32 + 2 * q];

#pragma unroll
        for (int ks = 0; ks < 4; ks++) {
            const int ca = (ks ^ rca) << 3;
            const int cb = (ks ^ rcb) << 3;
            float2 a02[4], a13[4], b01[4];
#pragma unroll
            for (int mt = 0; mt < 4; mt++) {
                a02[mt] = *(const float2*)&pa[(mt * 16) * 32 + ca];       // (a0, a2)
                a13[mt] = *(const float2*)&pa[(mt * 16 + 8) * 32 + ca];   // (a1, a3)
            }
#pragma unroll
            for (int nt = 0; nt < 4; nt++)
                b01[nt] = *(const float2*)&pb[(nt * 8) * 32 + cb];        // (b0, b1)
#pragma unroll
            for (int mt = 0; mt < 4; mt++)
#pragma unroll
                for (int nt = 0; nt < 4; nt++)
                    mma8f(c[mt][nt], a02[mt].x, a13[mt].x, a02[mt].y, a13[mt].y,
                          b01[nt].x, b01[nt].y);
        }
        s = (s + 1) % 3;
    }

    const float scale = (FUSED && z == 0) ? qscale : 1.0f;
#pragma unroll
    for (int mt = 0; mt < 4; mt++) {
#pragma unroll
        for (int hr = 0; hr < 2; hr++) {
            int row = row0 + wm + mt * 16 + g + hr * 8;
#pragma unroll
            for (int nt = 0; nt < 4; nt++) {
                int col = col0 + wn + nt * 8 + q * 2;
                float vx = c[mt][nt][hr * 2] * scale;
                float vy = c[mt][nt][hr * 2 + 1] * scale;
                if (!FUSED) {
                    *(float2*)&C0[(size_t)row * N + col] = make_float2(vx, vy);
                } else {
                    vx = to_tf32(vx); vy = to_tf32(vy);
                    int head = col >> 6, d0 = col & 63, d1 = d0 + 1;
                    if (z == 2) {
                        C2[((size_t)(head * 64 + d0)) * M + row] = vx;  // plain transposed
                        C2[((size_t)(head * 64 + d1)) * M + row] = vy;
                    } else {
                        float* C = (z == 0) ? C0 : C1;
                        size_t base = ((size_t)head * M + row) * 64;
                        C[base + ((d0 & ~7) | perm8(d0 & 7))] = vx;  // head-d permuted
                        C[base + ((d1 & ~7) | perm8(d1 & 7))] = vy;
                    }
                }
            }
        }
    }
}

// ---------------------------------------------------------------------------
// Tensor-core flash attention. 1D grid of 512 in GLOBAL LPT order:
// head = bid & 15, bx = 31 - (bid >> 4) -> all heads' largest blocks launch
// first, strictly descending work, minimizing wave-2 makespan.
// ---------------------------------------------------------------------------
#define PADK 72
#define AT_QOFF   0
#define AT_KOFF   (128 * PADK)
#define AT_VOFF   (AT_KOFF + 2 * 64 * PADK)
#define AT_FLOATS (AT_VOFF + 2 * 64 * PADK)   // 27648 floats = 110592 B

__global__ __launch_bounds__(256, 2) void attn_mma() {
    extern __shared__ float sm[];
    const uint32_t sb = smem_u32(sm);
    const int bid = blockIdx.x;
    const int h  = bid & 15;
    const int bx = 31 - (bid >> 4);   // global descending-work order
    const int i0 = bx * 128;
    const int tid = threadIdx.x;
    const int w = tid >> 5;
    const int lane = tid & 31;
    const int g = lane >> 2, q = lane & 3;
    const int qr = w * 16;
    const float slope2 = ex2(-0.5f * (float)(h + 1)) * LOG2E;

    const float* Qs = sm + AT_QOFF;

    auto load_tile = [&](int t, int s) {
        const int j0 = t * 64;
        const float* kp = g_k + ((size_t)h * L_SEQ + j0) * HDIM;
        const float* vp = g_v + (size_t)h * HDIM * L_SEQ + j0;
        const uint32_t kd = sb + (AT_KOFF + s * 64 * PADK) * 4u;
        const uint32_t vd = sb + (AT_VOFF + s * 64 * PADK) * 4u;
#pragma unroll
        for (int i = 0; i < 4; i++) {
            int cc = tid + i * 256;
            int row = cc >> 4, c16 = cc & 15;
            asm volatile("cp.async.cg.shared.global [%0], [%1], 16;"
                         :: "r"(kd + (uint32_t)(row * PADK + c16 * 4) * 4u),
                            "l"(kp + (size_t)row * HDIM + c16 * 4));
            asm volatile("cp.async.cg.shared.global [%0], [%1], 16;"
                         :: "r"(vd + (uint32_t)(row * PADK + c16 * 4) * 4u),
                            "l"(vp + (size_t)row * L_SEQ + c16 * 4));
        }
        asm volatile("cp.async.commit_group;");
    };

    const int ntiles = 2 * bx + 2;
    const int tstart = ntiles - 1;

    {
        const float* qp = g_q + ((size_t)h * L_SEQ + i0) * HDIM;
        const uint32_t qd = sb + AT_QOFF * 4u;
#pragma unroll
        for (int i = 0; i < 8; i++) {
            int cc = tid + i * 256;
            int row = cc >> 4, c16 = cc & 15;
            asm volatile("cp.async.cg.shared.global [%0], [%1], 16;"
                         :: "r"(qd + (uint32_t)(row * PADK + c16 * 4) * 4u),
                            "l"(qp + (size_t)row * HDIM + c16 * 4));
        }
        load_tile(tstart, tstart & 1);
    }

    float mA = -INFINITY, mB = -INFINITY, lA = 0.f, lB = 0.f;
    float O[8][4];
#pragma unroll
    for (int nt = 0; nt < 8; nt++)
#pragma unroll
        for (int r = 0; r < 4; r++) O[nt][r] = 0.f;

    const int iA = i0 + qr + g;
    const int iB = iA + 8;

    for (int t = tstart; t >= 0; t--) {
        if (t > 0) {
            load_tile(t - 1, (t - 1) & 1);
            asm volatile("cp.async.wait_group 1;");
        } else {
            asm volatile("cp.async.wait_group 0;");
        }
        __syncthreads();

        const int j0 = t * 64;
        if (j0 <= i0 + qr + 15) {
            const float* Ks = sm + AT_KOFF + (t & 1) * 64 * PADK;
            const float* Vs = sm + AT_VOFF + (t & 1) * 64 * PADK;

            // ---- S = Q K^T (paired d-layout: LDS.64 frags) ----
            float s[8][4];
#pragma unroll
            for (int nt = 0; nt < 8; nt++)
#pragma unroll
                for (int r = 0; r < 4; r++) s[nt][r] = 0.f;

#pragma unroll
            for (int ks = 0; ks < 8; ks++) {
                float2 qa = *(const float2*)&Qs[(qr + g) * PADK + ks * 8 + 2 * q];
                float2 qb = *(const float2*)&Qs[(qr + g + 8) * PADK + ks * 8 + 2 * q];
                uint32_t a0 = __float_as_uint(qa.x), a2 = __float_as_uint(qa.y);
                uint32_t a1 = __float_as_uint(qb.x), a3 = __float_as_uint(qb.y);
#pragma unroll
                for (int nt = 0; nt < 8; nt++) {
                    float2 kb = *(const float2*)&Ks[(nt * 8 + g) * PADK + ks * 8 + 2 * q];
                    mma8(s[nt], a0, a1, a2, a3,
                         __float_as_uint(kb.x), __float_as_uint(kb.y));
                }
            }

            // ---- ALiBi + causal ----
            const bool needmask = (j0 + 63 > i0 + qr);
#pragma unroll
            for (int nt = 0; nt < 8; nt++) {
                int j = j0 + nt * 8 + 2 * q;
                s[nt][0] -= slope2 * (float)(iA - j);
                s[nt][1] -= slope2 * (float)(iA - j - 1);
                s[nt][2] -= slope2 * (float)(iB - j);
                s[nt][3] -= slope2 * (float)(iB - j - 1);
                if (needmask) {
                    if (j > iA)     s[nt][0] = -INFINITY;
                    if (j + 1 > iA) s[nt][1] = -INFINITY;
                    if (j > iB)     s[nt][2] = -INFINITY;
                    if (j + 1 > iB) s[nt][3] = -INFINITY;
                }
            }

            // ---- online softmax (diagonal-first: rescale rarely fires) ----
            float mxA = -INFINITY, mxB = -INFINITY;
#pragma unroll
            for (int nt = 0; nt < 8; nt++) {
                mxA = fmaxf(mxA, fmaxf(s[nt][0], s[nt][1]));
                mxB = fmaxf(mxB, fmaxf(s[nt][2], s[nt][3]));
            }
            mxA = fmaxf(mxA, __shfl_xor_sync(0xffffffffu, mxA, 1));
            mxA = fmaxf(mxA, __shfl_xor_sync(0xffffffffu, mxA, 2));
            mxB = fmaxf(mxB, __shfl_xor_sync(0xffffffffu, mxB, 1));
            mxB = fmaxf(mxB, __shfl_xor_sync(0xffffffffu, mxB, 2));
            const float mAn = fmaxf(mA, mxA), mBn = fmaxf(mB, mxB);
            bool changed = (mAn != mA) || (mBn != mB);
            if (__any_sync(0xffffffffu, changed)) {
                const float cA = ex2(mA - mAn), cB = ex2(mB - mBn);
                mA = mAn; mB = mBn;
                lA *= cA; lB *= cB;
#pragma unroll
                for (int nt = 0; nt < 8; nt++) {
                    O[nt][0] *= cA; O[nt][1] *= cA;
                    O[nt][2] *= cB; O[nt][3] *= cB;
                }
            }
#pragma unroll
            for (int nt = 0; nt < 8; nt++) {
                float p0 = tf32_trunc(ex2(s[nt][0] - mA));
                float p1 = tf32_trunc(ex2(s[nt][1] - mA));
                float p2 = tf32_trunc(ex2(s[nt][2] - mB));
                float p3 = tf32_trunc(ex2(s[nt][3] - mB));
                s[nt][0] = p0; s[nt][1] = p1; s[nt][2] = p2; s[nt][3] = p3;
                lA += p0 + p1; lB += p2 + p3;
            }

            // ---- O += P V : shuffle-free, pair-interleaved k-ordering ----
#pragma unroll
            for (int ks = 0; ks < 8; ks++) {
                uint32_t a0 = __float_as_uint(s[ks][0]);
                uint32_t a1 = __float_as_uint(s[ks][2]);
                uint32_t a2 = __float_as_uint(s[ks][1]);
                uint32_t a3 = __float_as_uint(s[ks][3]);
#pragma unroll
                for (int nt = 0; nt < 8; nt++) {
                    float2 vb = *(const float2*)&Vs[(nt * 8 + g) * PADK + ks * 8 + 2 * q];
                    mma8(O[nt], a0, a1, a2, a3,
                         __float_as_uint(vb.x), __float_as_uint(vb.y));
                }
            }
        }
        __syncthreads();
    }

    lA += __shfl_xor_sync(0xffffffffu, lA, 1);
    lA += __shfl_xor_sync(0xffffffffu, lA, 2);
    lB += __shfl_xor_sync(0xffffffffu, lB, 1);
    lB += __shfl_xor_sync(0xffffffffu, lB, 2);
    const float invA = 1.0f / lA, invB = 1.0f / lB;
    // write g_attn with DMODEL-k pair-interleave (for the out-GEMM)
    const int p0 = perm8(2 * q), p1 = perm8(2 * q + 1);
#pragma unroll
    for (int nt = 0; nt < 8; nt++) {
        int colb = h * HDIM + nt * 8;
        g_attn[(size_t)iA * DMODEL + colb + p0] = to_tf32(O[nt][0] * invA);
        g_attn[(size_t)iA * DMODEL + colb + p1] = to_tf32(O[nt][1] * invA);
        g_attn[(size_t)iB * DMODEL + colb + p0] = to_tf32(O[nt][2] * invB);
        g_attn[(size_t)iB * DMODEL + colb + p1] = to_tf32(O[nt][3] * invB);
    }
}

// ---------------------------------------------------------------------------
extern "C" void kernel_launch(void* const* d_in, const int* in_sizes, int n_in,
                              void* d_out, int out_size) {
    const float* x  = (const float*)d_in[0];
    const float* qw = (const float*)d_in[1];
    const float* kw = (const float*)d_in[2];
    const float* vw = (const float*)d_in[3];
    const float* ow = (const float*)d_in[4];
    float* out = (float*)d_out;

    float *pq, *pk, *pv, *pa, *pwt, *pxr;
    cudaGetSymbolAddress((void**)&pq, g_q);
    cudaGetSymbolAddress((void**)&pk, g_k);
    cudaGetSymbolAddress((void**)&pv, g_v);
    cudaGetSymbolAddress((void**)&pa, g_attn);
    cudaGetSymbolAddress((void**)&pwt, g_wt);
    cudaGetSymbolAddress((void**)&pxr, g_xr);

    const int SMEM_ATTN = AT_FLOATS * 4;  // 110592 B
    cudaFuncSetAttribute(gemm_mma<true>,  cudaFuncAttributeMaxDynamicSharedMemorySize, SMEM_GEMM3);
    cudaFuncSetAttribute(gemm_mma<false>, cudaFuncAttributeMaxDynamicSharedMemorySize, SMEM_GEMM3);
    cudaFuncSetAttribute(attn_mma, cudaFuncAttributeMaxDynamicSharedMemorySize, SMEM_ATTN);

    round_x<<<(L_SEQ * DMODEL) / (256 * 8), 256>>>(x, pxr);
    dim3 tb(32, 8);
    dim3 tg(DMODEL / 32, DMODEL / 32, 4);
    transpose_w<<<tg, tb>>>(qw, kw, vw, ow, pwt);

    const float qscale = 0.125f * LOG2E;
    dim3 gqkv(DMODEL / 128, L_SEQ / 128, 3);
    gemm_mma<true><<<gqkv, 256, SMEM_GEMM3>>>(pxr, pwt, pq, pk, pv,
                                              L_SEQ, DMODEL, DMODEL, qscale);

    attn_mma<<<(L_SEQ / 128) * NHEADS, 256, SMEM_ATTN>>>();

    dim3 gout(DMODEL / 128, L_SEQ / 128, 1);
    gemm_mma<false><<<gout, 256, SMEM_GEMM3>>>(pa, pwt + 3 * (size_t)DMODEL * DMODEL,
                                               out, nullptr, nullptr,
                                               L_SEQ, DMODEL, DMODEL, 1.0f);
}

// round 16
// speedup vs baseline: 1.3135x; 1.0328x over previous
#include <cuda_runtime.h>
#include <math.h>
#include <stdint.h>

#define L_SEQ  4096
#define DMODEL 1024
#define NHEADS 16
#define HDIM   64
#define LOG2E  1.4426950408889634f

// Scratch (allocation-free rule: __device__ globals)
// Layouts (mma k-dim permutation-invariant when both operands agree):
//  * g_q/g_k: head-d dim pair-interleaved (perm8) -> attention QK frags = LDS.64
//  * g_v: plain transposed [h][d][seq] (QK C-frag == PV A-frag ordering)
//  * g_xr/g_wt/g_attn: DMODEL k-dim pair-interleaved (perm8) -> GEMM frags = LDS.64
__device__ float g_q[NHEADS * L_SEQ * HDIM];   // [h][seq][dperm], *0.125*log2e, tf32
__device__ float g_k[NHEADS * L_SEQ * HDIM];   // [h][seq][dperm], tf32
__device__ float g_v[NHEADS * HDIM * L_SEQ];   // [h][d][seq], tf32
__device__ float g_attn[L_SEQ * DMODEL];       // [seq][kperm], tf32
__device__ float g_wt[4 * DMODEL * DMODEL];    // transposed tf32 weights [N][Kperm]
__device__ float g_xr[L_SEQ * DMODEL];         // tf32-rounded x, [seq][kperm]

__device__ __forceinline__ uint32_t smem_u32(const void* p) {
    uint32_t a;
    asm("{ .reg .u64 t; cvta.to.shared.u64 t, %1; cvt.u32.u64 %0, t; }" : "=r"(a) : "l"(p));
    return a;
}
__device__ __forceinline__ float to_tf32(float x) {
    uint32_t r; asm("cvt.rna.tf32.f32 %0, %1;" : "=r"(r) : "f"(x));
    return __uint_as_float(r);
}
// cheap RZ truncation to tf32 bit-pattern (single LOP3 on the alu pipe)
__device__ __forceinline__ float tf32_trunc(float x) {
    return __uint_as_float(__float_as_uint(x) & 0xffffe000u);
}
__device__ __forceinline__ float ex2(float x) {
    float y; asm("ex2.approx.f32 %0, %1;" : "=f"(y) : "f"(x)); return y;
}
// logical slot l (0..7) -> physical position in pair-interleaved 8-group
__device__ __forceinline__ int perm8(int l) { return (l < 4) ? (2 * l) : (2 * (l - 4) + 1); }
__device__ __forceinline__ void mma8(float* c, uint32_t a0, uint32_t a1, uint32_t a2,
                                     uint32_t a3, uint32_t b0, uint32_t b1) {
    asm volatile(
        "mma.sync.aligned.m16n8k8.row.col.f32.tf32.tf32.f32 "
        "{%0,%1,%2,%3}, {%4,%5,%6,%7}, {%8,%9}, {%0,%1,%2,%3};"
        : "+f"(c[0]), "+f"(c[1]), "+f"(c[2]), "+f"(c[3])
        : "r"(a0), "r"(a1), "r"(a2), "r"(a3), "r"(b0), "r"(b1));
}
__device__ __forceinline__ void mma8f(float* c, float a0, float a1, float a2,
                                      float a3, float b0, float b1) {
    mma8(c, __float_as_uint(a0), __float_as_uint(a1), __float_as_uint(a2),
         __float_as_uint(a3), __float_as_uint(b0), __float_as_uint(b1));
}

// ---------------------------------------------------------------------------
// Fused prep: blocks [0,4096) transpose+round the 4 weight matrices
// (W[K][N] -> Wt[N][Kperm]); blocks [4096,6144) round+interleave x.
// One launch, both passes overlap across SMs.
// ---------------------------------------------------------------------------
__global__ __launch_bounds__(256) void prep(const float* __restrict__ x,
                                            float* __restrict__ xr,
                                            const float* __restrict__ w0,
                                            const float* __restrict__ w1,
                                            const float* __restrict__ w2,
                                            const float* __restrict__ w3,
                                            float* __restrict__ dst) {
    const int b = blockIdx.x;
    if (b < 4096) {
        __shared__ float tile[32][33];
        const int z = b >> 10;
        const int rem = b & 1023;
        const int bx = rem & 31, by = rem >> 5;
        const float* src = (z == 0) ? w0 : (z == 1) ? w1 : (z == 2) ? w2 : w3;
        float* d = dst + (size_t)z * DMODEL * DMODEL;
        const int tx = threadIdx.x & 31, ty = threadIdx.x >> 5;
        const int xcol = bx * 32 + tx;
        const int y0 = by * 32;
#pragma unroll
        for (int j = ty; j < 32; j += 8)
            tile[j][tx] = to_tf32(src[(size_t)(y0 + j) * DMODEL + xcol]);
        __syncthreads();
        const int xo_l = by * 32 + tx;                 // logical k index
        const int xo = (xo_l & ~7) | perm8(xo_l & 7);  // pair-interleaved
        const int yo0 = bx * 32;
#pragma unroll
        for (int j = ty; j < 32; j += 8)
            d[(size_t)(yo0 + j) * DMODEL + xo] = tile[tx][j];
    } else {
        int i = ((b - 4096) * 256 + threadIdx.x) * 8;
        float4 a = *(const float4*)&x[i];
        float4 bb = *(const float4*)&x[i + 4];
        *(float4*)&xr[i] =
            make_float4(to_tf32(a.x), to_tf32(bb.x), to_tf32(a.y), to_tf32(bb.y));
        *(float4*)&xr[i + 4] =
            make_float4(to_tf32(a.z), to_tf32(bb.z), to_tf32(a.w), to_tf32(bb.w));
    }
}

// ---------------------------------------------------------------------------
// tf32 mma.sync GEMM: CTA 128x128x32, 8 warps, 3-stage cp.async pipeline.
// Global k-layout is pair-interleaved; smem stage is 128 rows x 32 floats with
// an 8-float-group XOR swizzle (group ^ (row&3)) -> LDS.64 fragment loads.
// FUSED: z=0 -> g_q (scaled, head-d perm8), z=1 -> g_k (head-d perm8),
//        z=2 -> g_v (plain transposed). All tf32-rounded.
// !FUSED: plain C[row*N+col].
// ---------------------------------------------------------------------------
#define GBK 32
#define STG_FLOATS (128 * 32)
#define SMEM_GEMM3 (3 * 2 * STG_FLOATS * 4)   // 98304 B

template <bool FUSED>
__global__ __launch_bounds__(256, 2)
void gemm_mma(const float* __restrict__ A, const float* __restrict__ WtBase,
              float* __restrict__ C0, float* __restrict__ C1, float* __restrict__ C2,
              int M, int N, int K, float qscale) {
    extern __shared__ float smf[];
    const uint32_t sbase = smem_u32(smf);
    const int tid = threadIdx.x;
    const int wid = tid >> 5;
    const int lane = tid & 31;
    const int row0 = blockIdx.y * 128;
    const int col0 = blockIdx.x * 128;
    const int z = FUSED ? (int)blockIdx.z : 0;
    const float* Bt = WtBase + (size_t)z * DMODEL * DMODEL;
    const int wm = (wid & 1) * 64;
    const int wn = (wid >> 1) * 32;
    const int g = lane >> 2;
    const int q = lane & 3;

    const int l_row = tid >> 3;       // + 32*i
    const int l_c   = tid & 7;        // 16B chunk index within row
    const uint32_t c_off =
        (uint32_t)((((l_c >> 1) ^ (l_row & 3)) << 3) + ((l_c & 1) << 2)) * 4u;

    float c[4][4][4];
#pragma unroll
    for (int mt = 0; mt < 4; mt++)
#pragma unroll
        for (int nt = 0; nt < 4; nt++)
#pragma unroll
            for (int r = 0; r < 4; r++) c[mt][nt][r] = 0.f;

    auto stage_load = [&](int kb, int s) {
        const int k0 = kb * GBK;
#pragma unroll
        for (int i = 0; i < 4; i++) {
            int r = l_row + i * 32;
            uint32_t da = sbase + (uint32_t)(s * 2 * STG_FLOATS + r * 32) * 4u + c_off;
            const float* ga = &A[(size_t)(row0 + r) * K + k0 + l_c * 4];
            asm volatile("cp.async.cg.shared.global [%0], [%1], 16;" :: "r"(da), "l"(ga));
            uint32_t db = da + (uint32_t)STG_FLOATS * 4u;
            const float* gb = &Bt[(size_t)(col0 + r) * K + k0 + l_c * 4];
            asm volatile("cp.async.cg.shared.global [%0], [%1], 16;" :: "r"(db), "l"(gb));
        }
        asm volatile("cp.async.commit_group;");
    };

    const int NK = K / GBK;
    stage_load(0, 0);
    stage_load(1, 1);

    const int rca = (wm + g) & 3;
    const int rcb = (wn + g) & 3;

    int s = 0;
    for (int kb = 0; kb < NK; kb++) {
        if (kb + 1 < NK) {
            asm volatile("cp.async.wait_group 1;");
        } else {
            asm volatile("cp.async.wait_group 0;");
        }
        __syncthreads();
        if (kb + 2 < NK) stage_load(kb + 2, (kb + 2) % 3);

        const float* As = smf + s * 2 * STG_FLOATS;
        const float* Bs = As + STG_FLOATS;
        const float* pa = &As[(wm + g) * 32 + 2 * q];
        const float* pb = &Bs[(wn + g) * 32 + 2 * q];

#pragma unroll
        for (int ks = 0; ks < 4; ks++) {
            const int ca = (ks ^ rca) << 3;
            const int cb = (ks ^ rcb) << 3;
            float2 a02[4], a13[4], b01[4];
#pragma unroll
            for (int mt = 0; mt < 4; mt++) {
                a02[mt] = *(const float2*)&pa[(mt * 16) * 32 + ca];       // (a0, a2)
                a13[mt] = *(const float2*)&pa[(mt * 16 + 8) * 32 + ca];   // (a1, a3)
            }
#pragma unroll
            for (int nt = 0; nt < 4; nt++)
                b01[nt] = *(const float2*)&pb[(nt * 8) * 32 + cb];        // (b0, b1)
#pragma unroll
            for (int mt = 0; mt < 4; mt++)
#pragma unroll
                for (int nt = 0; nt < 4; nt++)
                    mma8f(c[mt][nt], a02[mt].x, a13[mt].x, a02[mt].y, a13[mt].y,
                          b01[nt].x, b01[nt].y);
        }
        s = (s + 1) % 3;
    }

    const float scale = (FUSED && z == 0) ? qscale : 1.0f;
#pragma unroll
    for (int mt = 0; mt < 4; mt++) {
#pragma unroll
        for (int hr = 0; hr < 2; hr++) {
            int row = row0 + wm + mt * 16 + g + hr * 8;
#pragma unroll
            for (int nt = 0; nt < 4; nt++) {
                int col = col0 + wn + nt * 8 + q * 2;
                float vx = c[mt][nt][hr * 2] * scale;
                float vy = c[mt][nt][hr * 2 + 1] * scale;
                if (!FUSED) {
                    *(float2*)&C0[(size_t)row * N + col] = make_float2(vx, vy);
                } else {
                    vx = to_tf32(vx); vy = to_tf32(vy);
                    int head = col >> 6, d0 = col & 63, d1 = d0 + 1;
                    if (z == 2) {
                        C2[((size_t)(head * 64 + d0)) * M + row] = vx;  // plain transposed
                        C2[((size_t)(head * 64 + d1)) * M + row] = vy;
                    } else {
                        float* C = (z == 0) ? C0 : C1;
                        size_t base = ((size_t)head * M + row) * 64;
                        C[base + ((d0 & ~7) | perm8(d0 & 7))] = vx;  // head-d permuted
                        C[base + ((d1 & ~7) | perm8(d1 & 7))] = vy;
                    }
                }
            }
        }
    }
}

// ---------------------------------------------------------------------------
// Tensor-core flash attention. 1D grid of 512 in GLOBAL LPT order.
// ALiBi applied as s += slope2*(j - i0): the row-dependent part -slope2*(i-i0)
// is constant per query row and cancels exactly in softmax; anchoring at i0
// keeps contributing scores O(slope*128) so fp32 ulp stays ~3e-5.
// ---------------------------------------------------------------------------
#define PADK 72
#define AT_QOFF   0
#define AT_KOFF   (128 * PADK)
#define AT_VOFF   (AT_KOFF + 2 * 64 * PADK)
#define AT_FLOATS (AT_VOFF + 2 * 64 * PADK)   // 27648 floats = 110592 B

__global__ __launch_bounds__(256, 2) void attn_mma() {
    extern __shared__ float sm[];
    const uint32_t sb = smem_u32(sm);
    const int bid = blockIdx.x;
    const int h  = bid & 15;
    const int bx = 31 - (bid >> 4);   // global descending-work order
    const int i0 = bx * 128;
    const int tid = threadIdx.x;
    const int w = tid >> 5;
    const int lane = tid & 31;
    const int g = lane >> 2, q = lane & 3;
    const int qr = w * 16;
    const float slope2 = ex2(-0.5f * (float)(h + 1)) * LOG2E;

    const float* Qs = sm + AT_QOFF;

    auto load_tile = [&](int t, int s) {
        const int j0 = t * 64;
        const float* kp = g_k + ((size_t)h * L_SEQ + j0) * HDIM;
        const float* vp = g_v + (size_t)h * HDIM * L_SEQ + j0;
        const uint32_t kd = sb + (AT_KOFF + s * 64 * PADK) * 4u;
        const uint32_t vd = sb + (AT_VOFF + s * 64 * PADK) * 4u;
#pragma unroll
        for (int i = 0; i < 4; i++) {
            int cc = tid + i * 256;
            int row = cc >> 4, c16 = cc & 15;
            asm volatile("cp.async.cg.shared.global [%0], [%1], 16;"
                         :: "r"(kd + (uint32_t)(row * PADK + c16 * 4) * 4u),
                            "l"(kp + (size_t)row * HDIM + c16 * 4));
            asm volatile("cp.async.cg.shared.global [%0], [%1], 16;"
                         :: "r"(vd + (uint32_t)(row * PADK + c16 * 4) * 4u),
                            "l"(vp + (size_t)row * L_SEQ + c16 * 4));
        }
        asm volatile("cp.async.commit_group;");
    };

    const int ntiles = 2 * bx + 2;
    const int tstart = ntiles - 1;

    {
        const float* qp = g_q + ((size_t)h * L_SEQ + i0) * HDIM;
        const uint32_t qd = sb + AT_QOFF * 4u;
#pragma unroll
        for (int i = 0; i < 8; i++) {
            int cc = tid + i * 256;
            int row = cc >> 4, c16 = cc & 15;
            asm volatile("cp.async.cg.shared.global [%0], [%1], 16;"
                         :: "r"(qd + (uint32_t)(row * PADK + c16 * 4) * 4u),
                            "l"(qp + (size_t)row * HDIM + c16 * 4));
        }
        load_tile(tstart, tstart & 1);
    }

    float mA = -INFINITY, mB = -INFINITY, lA = 0.f, lB = 0.f;
    float O[8][4];
#pragma unroll
    for (int nt = 0; nt < 8; nt++)
#pragma unroll
        for (int r = 0; r < 4; r++) O[nt][r] = 0.f;

    const int iA = i0 + qr + g;
    const int iB = iA + 8;

    for (int t = tstart; t >= 0; t--) {
        if (t > 0) {
            load_tile(t - 1, (t - 1) & 1);
            asm volatile("cp.async.wait_group 1;");
        } else {
            asm volatile("cp.async.wait_group 0;");
        }
        __syncthreads();

        const int j0 = t * 64;
        if (j0 <= i0 + qr + 15) {
            const float* Ks = sm + AT_KOFF + (t & 1) * 64 * PADK;
            const float* Vs = sm + AT_VOFF + (t & 1) * 64 * PADK;

            // ---- S = Q K^T (paired d-layout: LDS.64 frags) ----
            float s[8][4];
#pragma unroll
            for (int nt = 0; nt < 8; nt++)
#pragma unroll
                for (int r = 0; r < 4; r++) s[nt][r] = 0.f;

#pragma unroll
            for (int ks = 0; ks < 8; ks++) {
                float2 qa = *(const float2*)&Qs[(qr + g) * PADK + ks * 8 + 2 * q];
                float2 qb = *(const float2*)&Qs[(qr + g + 8) * PADK + ks * 8 + 2 * q];
                uint32_t a0 = __float_as_uint(qa.x), a2 = __float_as_uint(qa.y);
                uint32_t a1 = __float_as_uint(qb.x), a3 = __float_as_uint(qb.y);
#pragma unroll
                for (int nt = 0; nt < 8; nt++) {
                    float2 kb = *(const float2*)&Ks[(nt * 8 + g) * PADK + ks * 8 + 2 * q];
                    mma8(s[nt], a0, a1, a2, a3,
                         __float_as_uint(kb.x), __float_as_uint(kb.y));
                }
            }

            // ---- ALiBi (row-invariant form) + causal ----
            const bool needmask = (j0 + 63 > i0 + qr);
            const float base = slope2 * (float)(j0 + 2 * q - i0);
#pragma unroll
            for (int nt = 0; nt < 8; nt++) {
                float aj  = fmaf(slope2, (float)(nt * 8), base);
                float aj1 = aj + slope2;
                s[nt][0] += aj;  s[nt][1] += aj1;
                s[nt][2] += aj;  s[nt][3] += aj1;
                if (needmask) {
                    int j = j0 + nt * 8 + 2 * q;
                    if (j > iA)     s[nt][0] = -INFINITY;
                    if (j + 1 > iA) s[nt][1] = -INFINITY;
                    if (j > iB)     s[nt][2] = -INFINITY;
                    if (j + 1 > iB) s[nt][3] = -INFINITY;
                }
            }

            // ---- online softmax (diagonal-first: rescale rarely fires) ----
            float mxA = -INFINITY, mxB = -INFINITY;
#pragma unroll
            for (int nt = 0; nt < 8; nt++) {
                mxA = fmaxf(mxA, fmaxf(s[nt][0], s[nt][1]));
                mxB = fmaxf(mxB, fmaxf(s[nt][2], s[nt][3]));
            }
            mxA = fmaxf(mxA, __shfl_xor_sync(0xffffffffu, mxA, 1));
            mxA = fmaxf(mxA, __shfl_xor_sync(0xffffffffu, mxA, 2));
            mxB = fmaxf(mxB, __shfl_xor_sync(0xffffffffu, mxB, 1));
            mxB = fmaxf(mxB, __shfl_xor_sync(0xffffffffu, mxB, 2));
            const float mAn = fmaxf(mA, mxA), mBn = fmaxf(mB, mxB);
            bool changed = (mAn != mA) || (mBn != mB);
            if (__any_sync(0xffffffffu, changed)) {
                const float cA = ex2(mA - mAn), cB = ex2(mB - mBn);
                mA = mAn; mB = mBn;
                lA *= cA; lB *= cB;
#pragma unroll
                for (int nt = 0; nt < 8; nt++) {
                    O[nt][0] *= cA; O[nt][1] *= cA;
                    O[nt][2] *= cB; O[nt][3] *= cB;
                }
            }
#pragma unroll
            for (int nt = 0; nt < 8; nt++) {
                float p0 = tf32_trunc(ex2(s[nt][0] - mA));
                float p1 = tf32_trunc(ex2(s[nt][1] - mA));
                float p2 = tf32_trunc(ex2(s[nt][2] - mB));
                float p3 = tf32_trunc(ex2(s[nt][3] - mB));
                s[nt][0] = p0; s[nt][1] = p1; s[nt][2] = p2; s[nt][3] = p3;
                lA += p0 + p1; lB += p2 + p3;
            }

            // ---- O += P V : shuffle-free, pair-interleaved k-ordering ----
#pragma unroll
            for (int ks = 0; ks < 8; ks++) {
                uint32_t a0 = __float_as_uint(s[ks][0]);
                uint32_t a1 = __float_as_uint(s[ks][2]);
                uint32_t a2 = __float_as_uint(s[ks][1]);
                uint32_t a3 = __float_as_uint(s[ks][3]);
#pragma unroll
                for (int nt = 0; nt < 8; nt++) {
                    float2 vb = *(const float2*)&Vs[(nt * 8 + g) * PADK + ks * 8 + 2 * q];
                    mma8(O[nt], a0, a1, a2, a3,
                         __float_as_uint(vb.x), __float_as_uint(vb.y));
                }
            }
        }
        __syncthreads();
    }

    lA += __shfl_xor_sync(0xffffffffu, lA, 1);
    lA += __shfl_xor_sync(0xffffffffu, lA, 2);
    lB += __shfl_xor_sync(0xffffffffu, lB, 1);
    lB += __shfl_xor_sync(0xffffffffu, lB, 2);
    const float invA = 1.0f / lA, invB = 1.0f / lB;
    // write g_attn with DMODEL-k pair-interleave (for the out-GEMM)
    const int p0 = perm8(2 * q), p1 = perm8(2 * q + 1);
#pragma unroll
    for (int nt = 0; nt < 8; nt++) {
        int colb = h * HDIM + nt * 8;
        g_attn[(size_t)iA * DMODEL + colb + p0] = to_tf32(O[nt][0] * invA);
        g_attn[(size_t)iA * DMODEL + colb + p1] = to_tf32(O[nt][1] * invA);
        g_attn[(size_t)iB * DMODEL + colb + p0] = to_tf32(O[nt][2] * invB);
        g_attn[(size_t)iB * DMODEL + colb + p1] = to_tf32(O[nt][3] * invB);
    }
}

// ---------------------------------------------------------------------------
extern "C" void kernel_launch(void* const* d_in, const int* in_sizes, int n_in,
                              void* d_out, int out_size) {
    const float* x  = (const float*)d_in[0];
    const float* qw = (const float*)d_in[1];
    const float* kw = (const float*)d_in[2];
    const float* vw = (const float*)d_in[3];
    const float* ow = (const float*)d_in[4];
    float* out = (float*)d_out;

    float *pq, *pk, *pv, *pa, *pwt, *pxr;
    cudaGetSymbolAddress((void**)&pq, g_q);
    cudaGetSymbolAddress((void**)&pk, g_k);
    cudaGetSymbolAddress((void**)&pv, g_v);
    cudaGetSymbolAddress((void**)&pa, g_attn);
    cudaGetSymbolAddress((void**)&pwt, g_wt);
    cudaGetSymbolAddress((void**)&pxr, g_xr);

    const int SMEM_ATTN = AT_FLOATS * 4;  // 110592 B
    cudaFuncSetAttribute(gemm_mma<true>,  cudaFuncAttributeMaxDynamicSharedMemorySize, SMEM_GEMM3);
    cudaFuncSetAttribute(gemm_mma<false>, cudaFuncAttributeMaxDynamicSharedMemorySize, SMEM_GEMM3);
    cudaFuncSetAttribute(attn_mma, cudaFuncAttributeMaxDynamicSharedMemorySize, SMEM_ATTN);

    // Fused prep: 4096 transpose blocks + 2048 round blocks
    prep<<<4096 + (L_SEQ * DMODEL) / (256 * 8), 256>>>(x, pxr, qw, kw, vw, ow, pwt);

    const float qscale = 0.125f * LOG2E;
    dim3 gqkv(DMODEL / 128, L_SEQ / 128, 3);
    gemm_mma<true><<<gqkv, 256, SMEM_GEMM3>>>(pxr, pwt, pq, pk, pv,
                                              L_SEQ, DMODEL, DMODEL, qscale);

    attn_mma<<<(L_SEQ / 128) * NHEADS, 256, SMEM_ATTN>>>();

    dim3 gout(DMODEL / 128, L_SEQ / 128, 1);
    gemm_mma<false><<<gout, 256, SMEM_GEMM3>>>(pa, pwt + 3 * (size_t)DMODEL * DMODEL,
                                               out, nullptr, nullptr,
                                               L_SEQ, DMODEL, DMODEL, 1.0f);
}